// round 8
// baseline (speedup 1.0000x reference)
#include <cuda_runtime.h>
#include <math.h>

#define RES   160
#define R3    (RES*RES*RES)
#define NRAY  2048
#define NS    558
#define NEARC 0.05f
#define FARC  3.5f
#define BGC   1.0f
#define STEPW 0.00625f                 /* STEPSIZE * VOXEL = 0.5 * 0.0125 */
#define ACT_SHIFT -4.5951198501345898f /* log(1/(1-0.01)-1) */

typedef unsigned long long u64;

// ---- packed f32x2 helpers (Blackwell-only; ptxas never auto-fuses FFMA2) ----
__device__ __forceinline__ u64 pk2(float lo, float hi) {
    u64 r; asm("mov.b64 %0, {%1, %2};" : "=l"(r) : "f"(lo), "f"(hi)); return r;
}
__device__ __forceinline__ void upk2(u64 v, float& lo, float& hi) {
    asm("mov.b64 {%0, %1}, %2;" : "=f"(lo), "=f"(hi) : "l"(v));
}
__device__ __forceinline__ void fma2(u64& d, u64 a, u64 b) {
    asm("fma.rn.f32x2 %0, %1, %2, %0;" : "+l"(d) : "l"(a), "l"(b));
}

// ---- device scratch (static; no allocations allowed) ----
__device__ float  g_grid_t[(size_t)R3 * 12];   // channel-last grid, 196.6 MB
__device__ float4 g_scratch[NRAY * NS];        // {alpha, r, g, b} per sample
__device__ float  g_att[NRAY * NS];            // att1 per sample; -1 marks OOB
__device__ float4 g_lat[(size_t)NRAY * NS * 3];// latent 12f per sample (3 x float4)
__device__ float  g_rayinfo[NRAY * 4];         // tmin, |d|, mask, pad
__device__ float  g_dbias[NRAY * 16];          // per-ray dir-layer1 bias (emb folded)

// =====================================================================
// Kernel 0: transpose grid (C,R,R,R) -> (R,R,R,C); 4 voxels per thread
// =====================================================================
__global__ __launch_bounds__(256) void k_transpose(const float* __restrict__ g) {
    int v4 = blockIdx.x * blockDim.x + threadIdx.x;
    if (v4 >= R3/4) return;
    size_t v = (size_t)v4 * 4;
    float4 a[12];
#pragma unroll
    for (int c = 0; c < 12; c++)
        a[c] = __ldg(reinterpret_cast<const float4*>(g + (size_t)c * R3 + v));
    float4* dst = reinterpret_cast<float4*>(g_grid_t + v * 12);
#pragma unroll
    for (int k = 0; k < 4; k++) {
        float vals[12];
#pragma unroll
        for (int c = 0; c < 12; c++)
            vals[c] = (k == 0) ? a[c].x : (k == 1) ? a[c].y : (k == 2) ? a[c].z : a[c].w;
        dst[k*3+0] = make_float4(vals[0], vals[1], vals[2],  vals[3]);
        dst[k*3+1] = make_float4(vals[4], vals[5], vals[6],  vals[7]);
        dst[k*3+2] = make_float4(vals[8], vals[9], vals[10], vals[11]);
    }
}

// =====================================================================
// Kernel 1: per-ray precompute
// =====================================================================
__global__ void k_raypre(const float* __restrict__ ro, const float* __restrict__ rd,
                         const float* __restrict__ vd, const float* __restrict__ dw1,
                         const float* __restrict__ db1) {
    int r = blockIdx.x * blockDim.x + threadIdx.x;
    if (r >= NRAY) return;
    float ox = ro[3*r], oy = ro[3*r+1], oz = ro[3*r+2];
    float dx = rd[3*r], dy = rd[3*r+1], dz = rd[3*r+2];
    float vx = (dx == 0.f) ? 1e-6f : dx;
    float vy = (dy == 0.f) ? 1e-6f : dy;
    float vz = (dz == 0.f) ? 1e-6f : dz;
    float rax = (1.f - ox) / vx, rbx = (-1.f - ox) / vx;
    float ray_ = (1.f - oy) / vy, rby = (-1.f - oy) / vy;
    float raz = (1.f - oz) / vz, rbz = (-1.f - oz) / vz;
    float tmn = fmaxf(fmaxf(fminf(rax, rbx), fminf(ray_, rby)), fminf(raz, rbz));
    float tmx = fminf(fminf(fmaxf(rax, rbx), fmaxf(ray_, rby)), fmaxf(raz, rbz));
    tmn = fminf(fmaxf(tmn, NEARC), FARC);
    tmx = fminf(fmaxf(tmx, NEARC), FARC);
    float mask = (tmx <= tmn) ? 1.f : 0.f;
    float nn = sqrtf(dx*dx + dy*dy + dz*dz);
    g_rayinfo[4*r+0] = tmn;
    g_rayinfo[4*r+1] = nn;
    g_rayinfo[4*r+2] = mask;
    g_rayinfo[4*r+3] = 0.f;

    float wx = vd[3*r], wy = vd[3*r+1], wz = vd[3*r+2];
    float emb[39];
    emb[0] = wx; emb[1] = wy; emb[2] = wz;
    float f = 1.f;
#pragma unroll
    for (int l = 0; l < 6; l++) {
        emb[3+6*l+0] = sinf(wx*f); emb[3+6*l+1] = sinf(wy*f); emb[3+6*l+2] = sinf(wz*f);
        emb[3+6*l+3] = cosf(wx*f); emb[3+6*l+4] = cosf(wy*f); emb[3+6*l+5] = cosf(wz*f);
        f *= 2.f;
    }
#pragma unroll
    for (int j = 0; j < 16; j++) {
        float acc = db1[j];
#pragma unroll
        for (int k = 0; k < 39; k++) acc += emb[k] * dw1[(15+k)*16 + j];
        g_dbias[16*r + j] = acc;
    }
}

// ---- shared packed-MLP building blocks ----
template<int IN, int OUTH>
__device__ __forceinline__ void layer2(const float* __restrict__ x,
                                       const float* __restrict__ sw_w,
                                       const float* __restrict__ sw_b,
                                       u64* acc) {
    const u64* b2 = reinterpret_cast<const u64*>(sw_b);
#pragma unroll
    for (int j = 0; j < OUTH; j++) acc[j] = b2[j];
#pragma unroll
    for (int i = 0; i < IN; i++) {
        u64 xb = pk2(x[i], x[i]);
        const ulonglong2* w = reinterpret_cast<const ulonglong2*>(sw_w + i * (2*OUTH));
#pragma unroll
        for (int j = 0; j < OUTH/2; j++) {
            ulonglong2 ww = w[j];
            fma2(acc[2*j+0], xb, ww.x);
            fma2(acc[2*j+1], xb, ww.y);
        }
    }
}

template<int OUTH>
__device__ __forceinline__ void relu_unpack(const u64* acc, float* out) {
#pragma unroll
    for (int j = 0; j < OUTH; j++) {
        float a, b; upk2(acc[j], a, b);
        out[2*j]   = fmaxf(a, 0.f);
        out[2*j+1] = fmaxf(b, 0.f);
    }
}

// =====================================================================
// Kernel A1: trilerp + attention MLP -> g_att, g_lat
// shared offsets: aw1 0(480) ab1 480(32) aw2 512(1024) ab2 1536(32)
//                 aw3 1568(128) ab3 1696(4); total 1700
// =====================================================================
__global__ __launch_bounds__(128) void k_A1(
    const float* __restrict__ ro, const float* __restrict__ rd,
    const float* __restrict__ aw1, const float* __restrict__ ab1,
    const float* __restrict__ aw2, const float* __restrict__ ab2,
    const float* __restrict__ aw3, const float* __restrict__ ab3)
{
    __shared__ __align__(16) float sw[1700];
    __shared__ float s_ray[9];
    {
        int t = threadIdx.x;
        for (int i = t; i < 480;  i += 128) sw[0 + i]    = aw1[i];
        for (int i = t; i < 32;   i += 128) sw[480 + i]  = ab1[i];
        for (int i = t; i < 1024; i += 128) sw[512 + i]  = aw2[i];
        for (int i = t; i < 32;   i += 128) sw[1536 + i] = ab2[i];
        for (int i = t; i < 128;  i += 128) sw[1568 + i] = aw3[i];
        for (int i = t; i < 4;    i += 128) sw[1696 + i] = ab3[i];
        int ray0 = blockIdx.x;
        if (t < 3)  s_ray[t] = g_rayinfo[4*ray0 + t];
        if (t >= 3 && t < 6) s_ray[t] = ro[3*ray0 + (t-3)];
        if (t >= 6 && t < 9) s_ray[t] = rd[3*ray0 + (t-6)];
    }
    __syncthreads();

    int ray = blockIdx.x;
    float tmn = s_ray[0], rn = s_ray[1], mask = s_ray[2];
    float rinv = STEPW / rn;
    float ox = s_ray[3], oy = s_ray[4], oz = s_ray[5];
    float ddx = s_ray[6], ddy = s_ray[7], ddz = s_ray[8];

    for (int s = threadIdx.x; s < NS; s += 128) {
        int oi = ray * NS + s;
        float it = tmn + rinv * (float)s;
        float px = ox + ddx * it;
        float py = oy + ddy * it;
        float pz = oz + ddz * it;
        bool inb = (mask == 0.f) &&
                   px >= -1.f && px <= 1.f &&
                   py >= -1.f && py <= 1.f &&
                   pz >= -1.f && pz <= 1.f;
        if (!inb) { g_att[oi] = -1.f; continue; }

        // ---- trilinear from channel-last grid ----
        float gx = (px + 1.f) * 0.5f * 159.f;
        float gy = (py + 1.f) * 0.5f * 159.f;
        float gz = (pz + 1.f) * 0.5f * 159.f;
        float fx0 = floorf(gx), fy0 = floorf(gy), fz0 = floorf(gz);
        float wx1 = gx - fx0, wy1 = gy - fy0, wz1 = gz - fz0;
        float wx0 = 1.f - wx1, wy0 = 1.f - wy1, wz0 = 1.f - wz1;
        int ix0 = min(max((int)fx0, 0), 159); int ix1 = min(ix0 + 1, 159);
        int iy0 = min(max((int)fy0, 0), 159); int iy1 = min(iy0 + 1, 159);
        int iz0 = min(max((int)fz0, 0), 159); int iz1 = min(iz0 + 1, 159);

        u64 lat2[6];
#pragma unroll
        for (int k = 0; k < 6; k++) lat2[k] = 0ull;

#define ADD_CORNER(X, Y, Z, W) {                                                     \
            const ulonglong2* gp = reinterpret_cast<const ulonglong2*>(              \
                g_grid_t + (size_t)((((X)*160 + (Y))*160) + (Z)) * 12);              \
            ulonglong2 A = __ldg(gp), B = __ldg(gp+1), C = __ldg(gp+2);              \
            float W_ = (W);                                                          \
            u64 wb = pk2(W_, W_);                                                    \
            fma2(lat2[0], wb, A.x); fma2(lat2[1], wb, A.y);                          \
            fma2(lat2[2], wb, B.x); fma2(lat2[3], wb, B.y);                          \
            fma2(lat2[4], wb, C.x); fma2(lat2[5], wb, C.y); }

        ADD_CORNER(ix0, iy0, iz0, wx0*wy0*wz0);
        ADD_CORNER(ix0, iy0, iz1, wx0*wy0*wz1);
        ADD_CORNER(ix0, iy1, iz0, wx0*wy1*wz0);
        ADD_CORNER(ix0, iy1, iz1, wx0*wy1*wz1);
        ADD_CORNER(ix1, iy0, iz0, wx1*wy0*wz0);
        ADD_CORNER(ix1, iy0, iz1, wx1*wy0*wz1);
        ADD_CORNER(ix1, iy1, iz0, wx1*wy1*wz0);
        ADD_CORNER(ix1, iy1, iz1, wx1*wy1*wz1);
#undef ADD_CORNER

        float lat[12];
#pragma unroll
        for (int k = 0; k < 6; k++) upk2(lat2[k], lat[2*k], lat[2*k+1]);

        // ---- attention MLP ----
        float xin[15];
        xin[0] = pz; xin[1] = py; xin[2] = px;
#pragma unroll
        for (int k = 0; k < 12; k++) xin[3+k] = lat[k];

        u64 acc16[16];
        float h1[32], h2[32];
        layer2<15, 16>(xin, &sw[0], &sw[480], acc16);
        relu_unpack<16>(acc16, h1);
        layer2<32, 16>(h1, &sw[512], &sw[1536], acc16);
        relu_unpack<16>(acc16, h2);

        u64 accO[2];
        layer2<32, 2>(h2, &sw[1568], &sw[1696], accO);
        float o0, o1, o2, o3;
        upk2(accO[0], o0, o1); upk2(accO[1], o2, o3);
        float mx = fmaxf(fmaxf(o0, o1), fmaxf(o2, o3));
        float e0 = expf(o0-mx), e1 = expf(o1-mx), e2 = expf(o2-mx), e3 = expf(o3-mx);
        float att1 = e1 / (e0 + e1 + e2 + e3);

        g_att[oi] = att1;
        g_lat[(size_t)oi*3+0] = make_float4(lat[0], lat[1], lat[2],  lat[3]);
        g_lat[(size_t)oi*3+1] = make_float4(lat[4], lat[5], lat[6],  lat[7]);
        g_lat[(size_t)oi*3+2] = make_float4(lat[8], lat[9], lat[10], lat[11]);
    }
}

// =====================================================================
// Kernel A2: pos MLP + dir MLP + activations -> g_scratch
// shared offsets: pw1 0(192) pb1 192(16) pw2 208(256) pb2 464(16)
//   pw3 480(256) pb3 736(16) dw1 752(240) dw2 992(256) db2 1248(16)
//   dw3 1264(256) db3 1520(16) dw4 1536(48) db4 1584(3); total 1587
// =====================================================================
__global__ __launch_bounds__(128) void k_A2(
    const float* __restrict__ pw1, const float* __restrict__ pb1,
    const float* __restrict__ pw2, const float* __restrict__ pb2,
    const float* __restrict__ pw3, const float* __restrict__ pb3,
    const float* __restrict__ dw1,
    const float* __restrict__ dw2, const float* __restrict__ db2,
    const float* __restrict__ dw3, const float* __restrict__ db3,
    const float* __restrict__ dw4, const float* __restrict__ db4)
{
    __shared__ __align__(16) float sw[1588];
    __shared__ __align__(16) float s_db[16];
    {
        int t = threadIdx.x;
        for (int i = t; i < 192;  i += 128) sw[0 + i]    = pw1[i];
        for (int i = t; i < 16;   i += 128) sw[192 + i]  = pb1[i];
        for (int i = t; i < 256;  i += 128) sw[208 + i]  = pw2[i];
        for (int i = t; i < 16;   i += 128) sw[464 + i]  = pb2[i];
        for (int i = t; i < 256;  i += 128) sw[480 + i]  = pw3[i];
        for (int i = t; i < 16;   i += 128) sw[736 + i]  = pb3[i];
        for (int i = t; i < 240;  i += 128) sw[752 + i]  = dw1[i];  // rows 0..14
        for (int i = t; i < 256;  i += 128) sw[992 + i]  = dw2[i];
        for (int i = t; i < 16;   i += 128) sw[1248 + i] = db2[i];
        for (int i = t; i < 256;  i += 128) sw[1264 + i] = dw3[i];
        for (int i = t; i < 16;   i += 128) sw[1520 + i] = db3[i];
        for (int i = t; i < 48;   i += 128) sw[1536 + i] = dw4[i];
        for (int i = t; i < 3;    i += 128) sw[1584 + i] = db4[i];
        if (t < 16) s_db[t] = g_dbias[16*blockIdx.x + t];
    }
    __syncthreads();

    int ray = blockIdx.x;
    for (int s = threadIdx.x; s < NS; s += 128) {
        int oi = ray * NS + s;
        float att1 = g_att[oi];
        if (att1 < 0.f) { g_scratch[oi] = make_float4(0.f, 0.f, 0.f, 0.f); continue; }

        float lat[12];
        float4 L0 = g_lat[(size_t)oi*3+0];
        float4 L1 = g_lat[(size_t)oi*3+1];
        float4 L2 = g_lat[(size_t)oi*3+2];
        lat[0]=L0.x; lat[1]=L0.y; lat[2]=L0.z;  lat[3]=L0.w;
        lat[4]=L1.x; lat[5]=L1.y; lat[6]=L1.z;  lat[7]=L1.w;
        lat[8]=L2.x; lat[9]=L2.y; lat[10]=L2.z; lat[11]=L2.w;

        // ---- pos MLP: 12 -> 16 -> 16 -> 16 ----
        u64 acc8[8];
        float p1[16], p2[16], p3[16];
        layer2<12, 8>(lat, &sw[0], &sw[192], acc8);
        relu_unpack<8>(acc8, p1);
        layer2<16, 8>(p1, &sw[208], &sw[464], acc8);
        relu_unpack<8>(acc8, p2);
        layer2<16, 8>(p2, &sw[480], &sw[736], acc8);
#pragma unroll
        for (int j = 0; j < 8; j++) upk2(acc8[j], p3[2*j], p3[2*j+1]);  // no relu

        // ---- dir MLP: [p3[1:16]; emb-folded bias] -> 16 -> 16 -> 16 -> 3 ----
        float d1[16], d2[16], d3[16];
        layer2<15, 8>(&p3[1], &sw[752], s_db, acc8);
        relu_unpack<8>(acc8, d1);
        layer2<16, 8>(d1, &sw[992], &sw[1248], acc8);
        relu_unpack<8>(acc8, d2);
        layer2<16, 8>(d2, &sw[1264], &sw[1520], acc8);
        relu_unpack<8>(acc8, d3);

        float r0 = sw[1584+0], r1 = sw[1584+1], r2 = sw[1584+2];
#pragma unroll
        for (int i = 0; i < 16; i++) {
            float xi = d3[i];
            r0 += xi * sw[1536 + i*3 + 0];
            r1 += xi * sw[1536 + i*3 + 1];
            r2 += xi * sw[1536 + i*3 + 2];
        }

        // ---- activations ----
        float dens = att1 * p3[0];
        float xs = dens + ACT_SHIFT;
        float sp = fmaxf(xs, 0.f) + log1pf(expf(-fabsf(xs)));   // softplus
        float alpha = 1.f - expf(-sp * 0.5f);
        float c0 = 1.f / (1.f + expf(-att1 * r0));
        float c1 = 1.f / (1.f + expf(-att1 * r1));
        float c2 = 1.f / (1.f + expf(-att1 * r2));

        g_scratch[oi] = make_float4(alpha, c0, c1, c2);
    }
}

// =====================================================================
// Kernel 3: warp-per-ray alpha compositing (shfl prefix-product scan)
// =====================================================================
__global__ __launch_bounds__(256) void k_phaseB(float* __restrict__ out) {
    int gid  = blockIdx.x * blockDim.x + threadIdx.x;
    int ray  = gid >> 5;
    int lane = gid & 31;
    if (ray >= NRAY) return;

    float tmn = g_rayinfo[4*ray], rn = g_rayinfo[4*ray+1];
    float base_depth = tmn * rn;

    float T = 1.f;
    float sr = 0.f, sg = 0.f, sb = 0.f, sd = 0.f, sa = 0.f;

    for (int c0 = 0; c0 < NS; c0 += 32) {
        int s = c0 + lane;
        float4 rec = make_float4(0.f, 0.f, 0.f, 0.f);
        if (s < NS) rec = g_scratch[ray*NS + s];
        float a = rec.x;
        float q = fmaxf(1.f - a, 1e-10f);
        float ip = q;
#pragma unroll
        for (int off = 1; off < 32; off <<= 1) {
            float v = __shfl_up_sync(0xFFFFFFFFu, ip, off);
            if (lane >= off) ip *= v;
        }
        float ep = __shfl_up_sync(0xFFFFFFFFu, ip, 1);
        if (lane == 0) ep = 1.f;
        float w = a * T * ep;
        sr += w * rec.y;
        sg += w * rec.z;
        sb += w * rec.w;
        sd += w * (base_depth + STEPW * (float)s);
        sa += w;
        T *= __shfl_sync(0xFFFFFFFFu, ip, 31);
    }

#pragma unroll
    for (int off = 16; off > 0; off >>= 1) {
        sr += __shfl_xor_sync(0xFFFFFFFFu, sr, off);
        sg += __shfl_xor_sync(0xFFFFFFFFu, sg, off);
        sb += __shfl_xor_sync(0xFFFFFFFFu, sb, off);
        sd += __shfl_xor_sync(0xFFFFFFFFu, sd, off);
        sa += __shfl_xor_sync(0xFFFFFFFFu, sa, off);
    }

    if (lane == 0) {
        float depth = sd + T * FARC;
        out[ray*6+0] = sr + T * BGC;
        out[ray*6+1] = sg + T * BGC;
        out[ray*6+2] = sb + T * BGC;
        out[ray*6+3] = depth;
        out[ray*6+4] = 1.f / depth;
        out[ray*6+5] = sa;
    }
}

// =====================================================================
extern "C" void kernel_launch(void* const* d_in, const int* in_sizes, int n_in,
                              void* d_out, int out_size) {
    const float* ro  = (const float*)d_in[0];
    const float* rd  = (const float*)d_in[1];
    const float* vd  = (const float*)d_in[2];
    const float* grd = (const float*)d_in[3];
    const float* aw1 = (const float*)d_in[4];
    const float* ab1 = (const float*)d_in[5];
    const float* aw2 = (const float*)d_in[6];
    const float* ab2 = (const float*)d_in[7];
    const float* aw3 = (const float*)d_in[8];
    const float* ab3 = (const float*)d_in[9];
    const float* pw1 = (const float*)d_in[10];
    const float* pb1 = (const float*)d_in[11];
    const float* pw2 = (const float*)d_in[12];
    const float* pb2 = (const float*)d_in[13];
    const float* pw3 = (const float*)d_in[14];
    const float* pb3 = (const float*)d_in[15];
    const float* dw1 = (const float*)d_in[16];
    const float* db1 = (const float*)d_in[17];
    const float* dw2 = (const float*)d_in[18];
    const float* db2 = (const float*)d_in[19];
    const float* dw3 = (const float*)d_in[20];
    const float* db3 = (const float*)d_in[21];
    const float* dw4 = (const float*)d_in[22];
    const float* db4 = (const float*)d_in[23];

    k_transpose<<<(R3/4 + 255) / 256, 256>>>(grd);
    k_raypre<<<(NRAY + 255) / 256, 256>>>(ro, rd, vd, dw1, db1);
    k_A1<<<NRAY, 128>>>(ro, rd, aw1, ab1, aw2, ab2, aw3, ab3);
    k_A2<<<NRAY, 128>>>(pw1, pb1, pw2, pb2, pw3, pb3,
                        dw1, dw2, db2, dw3, db3, dw4, db4);
    k_phaseB<<<(NRAY * 32) / 256, 256>>>((float*)d_out);
}

// round 10
// speedup vs baseline: 1.0869x; 1.0869x over previous
#include <cuda_runtime.h>
#include <math.h>

#define RES   160
#define R3    (RES*RES*RES)
#define NRAY  2048
#define NS    558
#define NEARC 0.05f
#define FARC  3.5f
#define BGC   1.0f
#define STEPW 0.00625f                 /* STEPSIZE * VOXEL = 0.5 * 0.0125 */
#define ACT_SHIFT -4.5951198501345898f /* log(1/(1-0.01)-1) */

typedef unsigned long long u64;
typedef unsigned int u32;

// ---- packed f32x2 helpers (Blackwell-only; ptxas never auto-fuses FFMA2) ----
__device__ __forceinline__ u64 pk2(float lo, float hi) {
    u64 r; asm("mov.b64 %0, {%1, %2};" : "=l"(r) : "f"(lo), "f"(hi)); return r;
}
__device__ __forceinline__ void upk2(u64 v, float& lo, float& hi) {
    asm("mov.b64 {%0, %1}, %2;" : "=f"(lo), "=f"(hi) : "l"(v));
}
__device__ __forceinline__ void fma2(u64& d, u64 a, u64 b) {
    asm("fma.rn.f32x2 %0, %1, %2, %0;" : "+l"(d) : "l"(a), "l"(b));
}

// ---- volatile shared loads: NOT hoistable/CSE-able by ptxas ----
__device__ __forceinline__ u32 smem_u32(const void* p) {
    u32 a;
    asm("{ .reg .u64 t; cvta.to.shared.u64 t, %1; cvt.u32.u64 %0, t; }"
        : "=r"(a) : "l"(p));
    return a;
}
__device__ __forceinline__ void lds_v2u64(u32 addr, u64& a, u64& b) {
    asm volatile("ld.shared.v2.b64 {%0, %1}, [%2];" : "=l"(a), "=l"(b) : "r"(addr));
}
__device__ __forceinline__ float lds_f32(u32 addr) {
    float v; asm volatile("ld.shared.f32 %0, [%1];" : "=f"(v) : "r"(addr)); return v;
}

// ---- device scratch (static; no allocations allowed) ----
__device__ float  g_grid_t[(size_t)R3 * 12];   // channel-last grid, 196.6 MB
__device__ float4 g_scratch[NRAY * NS];        // {alpha, r, g, b} per sample
__device__ float  g_rayinfo[NRAY * 4];         // tmin, |d|, mask, pad
__device__ float  g_dbias[NRAY * 16];          // per-ray dir-layer1 bias (emb folded)

// =====================================================================
// Kernel 0: transpose grid (C,R,R,R) -> (R,R,R,C); 4 voxels per thread
// =====================================================================
__global__ __launch_bounds__(256) void k_transpose(const float* __restrict__ g) {
    int v4 = blockIdx.x * blockDim.x + threadIdx.x;
    if (v4 >= R3/4) return;
    size_t v = (size_t)v4 * 4;
    float4 a[12];
#pragma unroll
    for (int c = 0; c < 12; c++)
        a[c] = __ldg(reinterpret_cast<const float4*>(g + (size_t)c * R3 + v));
    float4* dst = reinterpret_cast<float4*>(g_grid_t + v * 12);
#pragma unroll
    for (int k = 0; k < 4; k++) {
        float vals[12];
#pragma unroll
        for (int c = 0; c < 12; c++)
            vals[c] = (k == 0) ? a[c].x : (k == 1) ? a[c].y : (k == 2) ? a[c].z : a[c].w;
        dst[k*3+0] = make_float4(vals[0], vals[1], vals[2],  vals[3]);
        dst[k*3+1] = make_float4(vals[4], vals[5], vals[6],  vals[7]);
        dst[k*3+2] = make_float4(vals[8], vals[9], vals[10], vals[11]);
    }
}

// =====================================================================
// Kernel 1: per-ray precompute (tmin, |d|, mask, dir-layer1 bias)
// =====================================================================
__global__ void k_raypre(const float* __restrict__ ro, const float* __restrict__ rd,
                         const float* __restrict__ vd, const float* __restrict__ dw1,
                         const float* __restrict__ db1) {
    int r = blockIdx.x * blockDim.x + threadIdx.x;
    if (r >= NRAY) return;
    float ox = ro[3*r], oy = ro[3*r+1], oz = ro[3*r+2];
    float dx = rd[3*r], dy = rd[3*r+1], dz = rd[3*r+2];
    float vx = (dx == 0.f) ? 1e-6f : dx;
    float vy = (dy == 0.f) ? 1e-6f : dy;
    float vz = (dz == 0.f) ? 1e-6f : dz;
    float rax = (1.f - ox) / vx, rbx = (-1.f - ox) / vx;
    float ray_ = (1.f - oy) / vy, rby = (-1.f - oy) / vy;
    float raz = (1.f - oz) / vz, rbz = (-1.f - oz) / vz;
    float tmn = fmaxf(fmaxf(fminf(rax, rbx), fminf(ray_, rby)), fminf(raz, rbz));
    float tmx = fminf(fminf(fmaxf(rax, rbx), fmaxf(ray_, rby)), fmaxf(raz, rbz));
    tmn = fminf(fmaxf(tmn, NEARC), FARC);
    tmx = fminf(fmaxf(tmx, NEARC), FARC);
    float mask = (tmx <= tmn) ? 1.f : 0.f;
    float nn = sqrtf(dx*dx + dy*dy + dz*dz);
    g_rayinfo[4*r+0] = tmn;
    g_rayinfo[4*r+1] = nn;
    g_rayinfo[4*r+2] = mask;
    g_rayinfo[4*r+3] = 0.f;

    float wx = vd[3*r], wy = vd[3*r+1], wz = vd[3*r+2];
    float emb[39];
    emb[0] = wx; emb[1] = wy; emb[2] = wz;
    float f = 1.f;
#pragma unroll
    for (int l = 0; l < 6; l++) {
        emb[3+6*l+0] = sinf(wx*f); emb[3+6*l+1] = sinf(wy*f); emb[3+6*l+2] = sinf(wz*f);
        emb[3+6*l+3] = cosf(wx*f); emb[3+6*l+4] = cosf(wy*f); emb[3+6*l+5] = cosf(wz*f);
        f *= 2.f;
    }
#pragma unroll
    for (int j = 0; j < 16; j++) {
        float acc = db1[j];
#pragma unroll
        for (int k = 0; k < 39; k++) acc += emb[k] * dw1[(15+k)*16 + j];
        g_dbias[16*r + j] = acc;
    }
}

// =====================================================================
// Kernel 2: per-sample MLP evaluation -> scratch {alpha, rgb}
// one block (128 thr) per ray; weights in shared, volatile LDS in loop
// =====================================================================
#define O_AW1 0
#define O_AB1 480
#define O_AW2 512
#define O_AB2 1536
#define O_AW3 1568
#define O_AB3 1696
#define O_PW1 1700
#define O_PB1 1892
#define O_PW2 1908
#define O_PB2 2164
#define O_PW3 2180
#define O_PB3 2436
#define O_DW1 2452
#define O_DW2 2692
#define O_DB2 2948
#define O_DW3 2964
#define O_DB3 3220
#define O_DW4 3236
#define O_DB4 3284
#define SW_TOT 3288

// packed layer, all weight/bias reads via volatile LDS (un-hoistable)
template<int IN, int OUTH>
__device__ __forceinline__ void layer2v(const float* __restrict__ x,
                                        u32 w_addr, u32 b_addr,
                                        u64* acc) {
#pragma unroll
    for (int j = 0; j < OUTH; j += 2)
        lds_v2u64(b_addr + j * 8, acc[j], acc[j+1]);
#pragma unroll
    for (int i = 0; i < IN; i++) {
        u64 xb = pk2(x[i], x[i]);
        u32 row = w_addr + i * (2*OUTH) * 4;
#pragma unroll
        for (int j = 0; j < OUTH/2; j++) {
            u64 w0, w1;
            lds_v2u64(row + j * 16, w0, w1);
            fma2(acc[2*j+0], xb, w0);
            fma2(acc[2*j+1], xb, w1);
        }
    }
}

template<int OUTH>
__device__ __forceinline__ void relu_unpack(const u64* acc, float* out) {
#pragma unroll
    for (int j = 0; j < OUTH; j++) {
        float a, b; upk2(acc[j], a, b);
        out[2*j]   = fmaxf(a, 0.f);
        out[2*j+1] = fmaxf(b, 0.f);
    }
}

__global__ __launch_bounds__(128) void k_phaseA(
    const float* __restrict__ ro, const float* __restrict__ rd,
    const float* __restrict__ aw1, const float* __restrict__ ab1,
    const float* __restrict__ aw2, const float* __restrict__ ab2,
    const float* __restrict__ aw3, const float* __restrict__ ab3,
    const float* __restrict__ pw1, const float* __restrict__ pb1,
    const float* __restrict__ pw2, const float* __restrict__ pb2,
    const float* __restrict__ pw3, const float* __restrict__ pb3,
    const float* __restrict__ dw1,
    const float* __restrict__ dw2, const float* __restrict__ db2,
    const float* __restrict__ dw3, const float* __restrict__ db3,
    const float* __restrict__ dw4, const float* __restrict__ db4)
{
    __shared__ __align__(16) float sw[SW_TOT];
    __shared__ __align__(16) float s_db[16];
    __shared__ float s_ray[9];
    {
        int t = threadIdx.x;
        for (int i = t; i < 480;  i += 128) sw[O_AW1 + i] = aw1[i];
        for (int i = t; i < 32;   i += 128) sw[O_AB1 + i] = ab1[i];
        for (int i = t; i < 1024; i += 128) sw[O_AW2 + i] = aw2[i];
        for (int i = t; i < 32;   i += 128) sw[O_AB2 + i] = ab2[i];
        for (int i = t; i < 128;  i += 128) sw[O_AW3 + i] = aw3[i];
        for (int i = t; i < 4;    i += 128) sw[O_AB3 + i] = ab3[i];
        for (int i = t; i < 192;  i += 128) sw[O_PW1 + i] = pw1[i];
        for (int i = t; i < 16;   i += 128) sw[O_PB1 + i] = pb1[i];
        for (int i = t; i < 256;  i += 128) sw[O_PW2 + i] = pw2[i];
        for (int i = t; i < 16;   i += 128) sw[O_PB2 + i] = pb2[i];
        for (int i = t; i < 256;  i += 128) sw[O_PW3 + i] = pw3[i];
        for (int i = t; i < 16;   i += 128) sw[O_PB3 + i] = pb3[i];
        for (int i = t; i < 240;  i += 128) sw[O_DW1 + i] = dw1[i];  // rows 0..14
        for (int i = t; i < 256;  i += 128) sw[O_DW2 + i] = dw2[i];
        for (int i = t; i < 16;   i += 128) sw[O_DB2 + i] = db2[i];
        for (int i = t; i < 256;  i += 128) sw[O_DW3 + i] = dw3[i];
        for (int i = t; i < 16;   i += 128) sw[O_DB3 + i] = db3[i];
        for (int i = t; i < 48;   i += 128) sw[O_DW4 + i] = dw4[i];
        for (int i = t; i < 3;    i += 128) sw[O_DB4 + i] = db4[i];
        int ray0 = blockIdx.x;
        if (t < 16) s_db[t] = g_dbias[16*ray0 + t];
        if (t < 3)  s_ray[t] = g_rayinfo[4*ray0 + t];
        if (t >= 3 && t < 6) s_ray[t] = ro[3*ray0 + (t-3)];
        if (t >= 6 && t < 9) s_ray[t] = rd[3*ray0 + (t-6)];
    }
    __syncthreads();

    const u32 SWA = smem_u32(sw);
    const u32 DBA = smem_u32(s_db);

    int ray = blockIdx.x;
    float tmn = s_ray[0], rn = s_ray[1], mask = s_ray[2];
    float rinv = STEPW / rn;
    float ox = s_ray[3], oy = s_ray[4], oz = s_ray[5];
    float ddx = s_ray[6], ddy = s_ray[7], ddz = s_ray[8];

    for (int s = threadIdx.x; s < NS; s += 128) {
        int oi = ray * NS + s;
        float it = tmn + rinv * (float)s;
        float px = ox + ddx * it;
        float py = oy + ddy * it;
        float pz = oz + ddz * it;
        bool inb = (mask == 0.f) &&
                   px >= -1.f && px <= 1.f &&
                   py >= -1.f && py <= 1.f &&
                   pz >= -1.f && pz <= 1.f;
        if (!inb) { g_scratch[oi] = make_float4(0.f, 0.f, 0.f, 0.f); continue; }

        // ---- trilinear from channel-last grid (packed accumulators) ----
        float gx = (px + 1.f) * 0.5f * 159.f;
        float gy = (py + 1.f) * 0.5f * 159.f;
        float gz = (pz + 1.f) * 0.5f * 159.f;
        float fx0 = floorf(gx), fy0 = floorf(gy), fz0 = floorf(gz);
        float wx1 = gx - fx0, wy1 = gy - fy0, wz1 = gz - fz0;
        float wx0 = 1.f - wx1, wy0 = 1.f - wy1, wz0 = 1.f - wz1;
        int ix0 = min(max((int)fx0, 0), 159); int ix1 = min(ix0 + 1, 159);
        int iy0 = min(max((int)fy0, 0), 159); int iy1 = min(iy0 + 1, 159);
        int iz0 = min(max((int)fz0, 0), 159); int iz1 = min(iz0 + 1, 159);

        u64 lat2[6];
#pragma unroll
        for (int k = 0; k < 6; k++) lat2[k] = 0ull;

#define ADD_CORNER(X, Y, Z, W) {                                                     \
            const ulonglong2* gp = reinterpret_cast<const ulonglong2*>(              \
                g_grid_t + (size_t)((((X)*160 + (Y))*160) + (Z)) * 12);              \
            ulonglong2 A = __ldg(gp), B = __ldg(gp+1), C = __ldg(gp+2);              \
            float W_ = (W);                                                          \
            u64 wb = pk2(W_, W_);                                                    \
            fma2(lat2[0], wb, A.x); fma2(lat2[1], wb, A.y);                          \
            fma2(lat2[2], wb, B.x); fma2(lat2[3], wb, B.y);                          \
            fma2(lat2[4], wb, C.x); fma2(lat2[5], wb, C.y); }

        ADD_CORNER(ix0, iy0, iz0, wx0*wy0*wz0);
        ADD_CORNER(ix0, iy0, iz1, wx0*wy0*wz1);
        ADD_CORNER(ix0, iy1, iz0, wx0*wy1*wz0);
        ADD_CORNER(ix0, iy1, iz1, wx0*wy1*wz1);
        ADD_CORNER(ix1, iy0, iz0, wx1*wy0*wz0);
        ADD_CORNER(ix1, iy0, iz1, wx1*wy0*wz1);
        ADD_CORNER(ix1, iy1, iz0, wx1*wy1*wz0);
        ADD_CORNER(ix1, iy1, iz1, wx1*wy1*wz1);
#undef ADD_CORNER

        float lat[12];
#pragma unroll
        for (int k = 0; k < 6; k++) upk2(lat2[k], lat[2*k], lat[2*k+1]);

        // ---- attention MLP: [pz,py,px, lat] (15) -> 32 -> 32 -> 4 -> softmax[1]
        float xin[15];
        xin[0] = pz; xin[1] = py; xin[2] = px;
#pragma unroll
        for (int k = 0; k < 12; k++) xin[3+k] = lat[k];

        u64 acc16[16];
        float h1[32], h2[32];
        layer2v<15, 16>(xin, SWA + O_AW1*4, SWA + O_AB1*4, acc16);
        relu_unpack<16>(acc16, h1);
        layer2v<32, 16>(h1, SWA + O_AW2*4, SWA + O_AB2*4, acc16);
        relu_unpack<16>(acc16, h2);

        u64 accO[2];
        layer2v<32, 2>(h2, SWA + O_AW3*4, SWA + O_AB3*4, accO);
        float o0, o1, o2, o3;
        upk2(accO[0], o0, o1); upk2(accO[1], o2, o3);
        float mx = fmaxf(fmaxf(o0, o1), fmaxf(o2, o3));
        float e0 = expf(o0-mx), e1 = expf(o1-mx), e2 = expf(o2-mx), e3 = expf(o3-mx);
        float att1 = e1 / (e0 + e1 + e2 + e3);

        // ---- pos MLP: lat (12) -> 16 -> 16 -> 16 ----
        u64 acc8[8];
        float p1[16], p2[16], p3[16];
        layer2v<12, 8>(lat, SWA + O_PW1*4, SWA + O_PB1*4, acc8);
        relu_unpack<8>(acc8, p1);
        layer2v<16, 8>(p1, SWA + O_PW2*4, SWA + O_PB2*4, acc8);
        relu_unpack<8>(acc8, p2);
        layer2v<16, 8>(p2, SWA + O_PW3*4, SWA + O_PB3*4, acc8);
#pragma unroll
        for (int j = 0; j < 8; j++) upk2(acc8[j], p3[2*j], p3[2*j+1]);  // no relu

        // ---- dir MLP: [p3[1:16] ; emb(folded bias)] -> 16 -> 16 -> 16 -> 3 ----
        float d1[16], d2[16], d3[16];
        layer2v<15, 8>(&p3[1], SWA + O_DW1*4, DBA, acc8);
        relu_unpack<8>(acc8, d1);
        layer2v<16, 8>(d1, SWA + O_DW2*4, SWA + O_DB2*4, acc8);
        relu_unpack<8>(acc8, d2);
        layer2v<16, 8>(d2, SWA + O_DW3*4, SWA + O_DB3*4, acc8);
        relu_unpack<8>(acc8, d3);

        float r0 = lds_f32(SWA + (O_DB4+0)*4);
        float r1 = lds_f32(SWA + (O_DB4+1)*4);
        float r2 = lds_f32(SWA + (O_DB4+2)*4);
#pragma unroll
        for (int i = 0; i < 16; i++) {
            float xi = d3[i];
            r0 += xi * lds_f32(SWA + (O_DW4 + i*3 + 0)*4);
            r1 += xi * lds_f32(SWA + (O_DW4 + i*3 + 1)*4);
            r2 += xi * lds_f32(SWA + (O_DW4 + i*3 + 2)*4);
        }

        // ---- activations ----
        float dens = att1 * p3[0];
        float xs = dens + ACT_SHIFT;
        float sp = fmaxf(xs, 0.f) + log1pf(expf(-fabsf(xs)));   // softplus
        float alpha = 1.f - expf(-sp * 0.5f);
        float c0 = 1.f / (1.f + expf(-att1 * r0));
        float c1 = 1.f / (1.f + expf(-att1 * r1));
        float c2 = 1.f / (1.f + expf(-att1 * r2));

        g_scratch[oi] = make_float4(alpha, c0, c1, c2);
    }
}

// =====================================================================
// Kernel 3: warp-per-ray alpha compositing (shfl prefix-product scan)
// =====================================================================
__global__ __launch_bounds__(256) void k_phaseB(float* __restrict__ out) {
    int gid  = blockIdx.x * blockDim.x + threadIdx.x;
    int ray  = gid >> 5;
    int lane = gid & 31;
    if (ray >= NRAY) return;

    float tmn = g_rayinfo[4*ray], rn = g_rayinfo[4*ray+1];
    float base_depth = tmn * rn;

    float T = 1.f;
    float sr = 0.f, sg = 0.f, sb = 0.f, sd = 0.f, sa = 0.f;

    for (int c0 = 0; c0 < NS; c0 += 32) {
        int s = c0 + lane;
        float4 rec = make_float4(0.f, 0.f, 0.f, 0.f);
        if (s < NS) rec = g_scratch[ray*NS + s];
        float a = rec.x;
        float q = fmaxf(1.f - a, 1e-10f);
        float ip = q;
#pragma unroll
        for (int off = 1; off < 32; off <<= 1) {
            float v = __shfl_up_sync(0xFFFFFFFFu, ip, off);
            if (lane >= off) ip *= v;
        }
        float ep = __shfl_up_sync(0xFFFFFFFFu, ip, 1);
        if (lane == 0) ep = 1.f;
        float w = a * T * ep;
        sr += w * rec.y;
        sg += w * rec.z;
        sb += w * rec.w;
        sd += w * (base_depth + STEPW * (float)s);
        sa += w;
        T *= __shfl_sync(0xFFFFFFFFu, ip, 31);
    }

#pragma unroll
    for (int off = 16; off > 0; off >>= 1) {
        sr += __shfl_xor_sync(0xFFFFFFFFu, sr, off);
        sg += __shfl_xor_sync(0xFFFFFFFFu, sg, off);
        sb += __shfl_xor_sync(0xFFFFFFFFu, sb, off);
        sd += __shfl_xor_sync(0xFFFFFFFFu, sd, off);
        sa += __shfl_xor_sync(0xFFFFFFFFu, sa, off);
    }

    if (lane == 0) {
        float depth = sd + T * FARC;
        out[ray*6+0] = sr + T * BGC;
        out[ray*6+1] = sg + T * BGC;
        out[ray*6+2] = sb + T * BGC;
        out[ray*6+3] = depth;
        out[ray*6+4] = 1.f / depth;
        out[ray*6+5] = sa;
    }
}

// =====================================================================
extern "C" void kernel_launch(void* const* d_in, const int* in_sizes, int n_in,
                              void* d_out, int out_size) {
    const float* ro  = (const float*)d_in[0];
    const float* rd  = (const float*)d_in[1];
    const float* vd  = (const float*)d_in[2];
    const float* grd = (const float*)d_in[3];
    const float* aw1 = (const float*)d_in[4];
    const float* ab1 = (const float*)d_in[5];
    const float* aw2 = (const float*)d_in[6];
    const float* ab2 = (const float*)d_in[7];
    const float* aw3 = (const float*)d_in[8];
    const float* ab3 = (const float*)d_in[9];
    const float* pw1 = (const float*)d_in[10];
    const float* pb1 = (const float*)d_in[11];
    const float* pw2 = (const float*)d_in[12];
    const float* pb2 = (const float*)d_in[13];
    const float* pw3 = (const float*)d_in[14];
    const float* pb3 = (const float*)d_in[15];
    const float* dw1 = (const float*)d_in[16];
    const float* db1 = (const float*)d_in[17];
    const float* dw2 = (const float*)d_in[18];
    const float* db2 = (const float*)d_in[19];
    const float* dw3 = (const float*)d_in[20];
    const float* db3 = (const float*)d_in[21];
    const float* dw4 = (const float*)d_in[22];
    const float* db4 = (const float*)d_in[23];

    k_transpose<<<(R3/4 + 255) / 256, 256>>>(grd);
    k_raypre<<<(NRAY + 255) / 256, 256>>>(ro, rd, vd, dw1, db1);
    k_phaseA<<<NRAY, 128>>>(ro, rd,
                            aw1, ab1, aw2, ab2, aw3, ab3,
                            pw1, pb1, pw2, pb2, pw3, pb3,
                            dw1, dw2, db2, dw3, db3, dw4, db4);
    k_phaseB<<<(NRAY * 32) / 256, 256>>>((float*)d_out);
}

// round 11
// speedup vs baseline: 1.0882x; 1.0012x over previous
#include <cuda_runtime.h>
#include <math.h>

#define RES   160
#define R3    (RES*RES*RES)
#define NRAY  2048
#define NS    558
#define NEARC 0.05f
#define FARC  3.5f
#define BGC   1.0f
#define STEPW 0.00625f                 /* STEPSIZE * VOXEL = 0.5 * 0.0125 */
#define ACT_SHIFT -4.5951198501345898f /* log(1/(1-0.01)-1) */

typedef unsigned long long u64;
typedef unsigned int u32;

// ---- packed f32x2 helpers (Blackwell-only; ptxas never auto-fuses FFMA2) ----
__device__ __forceinline__ u64 pk2(float lo, float hi) {
    u64 r; asm("mov.b64 %0, {%1, %2};" : "=l"(r) : "f"(lo), "f"(hi)); return r;
}
__device__ __forceinline__ void upk2(u64 v, float& lo, float& hi) {
    asm("mov.b64 {%0, %1}, %2;" : "=f"(lo), "=f"(hi) : "l"(v));
}
__device__ __forceinline__ void fma2(u64& d, u64 a, u64 b) {
    asm("fma.rn.f32x2 %0, %1, %2, %0;" : "+l"(d) : "l"(a), "l"(b));
}

// ---- device scratch (static; no allocations allowed) ----
__device__ float  g_grid_t[(size_t)R3 * 12];   // channel-last grid, 196.6 MB
__device__ float4 g_scratch[NRAY * NS];        // {alpha, r, g, b} per sample
__device__ float  g_rayinfo[NRAY * 4];         // tmin, |d|, mask, pad
__device__ float  g_dbias[NRAY * 16];          // per-ray dir-layer1 bias (emb folded)

// =====================================================================
// Kernel 0: transpose grid (C,R,R,R) -> (R,R,R,C); 4 voxels per thread
// =====================================================================
__global__ __launch_bounds__(256) void k_transpose(const float* __restrict__ g) {
    int v4 = blockIdx.x * blockDim.x + threadIdx.x;
    if (v4 >= R3/4) return;
    size_t v = (size_t)v4 * 4;
    float4 a[12];
#pragma unroll
    for (int c = 0; c < 12; c++)
        a[c] = __ldg(reinterpret_cast<const float4*>(g + (size_t)c * R3 + v));
    float4* dst = reinterpret_cast<float4*>(g_grid_t + v * 12);
#pragma unroll
    for (int k = 0; k < 4; k++) {
        float vals[12];
#pragma unroll
        for (int c = 0; c < 12; c++)
            vals[c] = (k == 0) ? a[c].x : (k == 1) ? a[c].y : (k == 2) ? a[c].z : a[c].w;
        dst[k*3+0] = make_float4(vals[0], vals[1], vals[2],  vals[3]);
        dst[k*3+1] = make_float4(vals[4], vals[5], vals[6],  vals[7]);
        dst[k*3+2] = make_float4(vals[8], vals[9], vals[10], vals[11]);
    }
}

// =====================================================================
// Kernel 1: per-ray precompute (tmin, |d|, mask, dir-layer1 bias)
// =====================================================================
__global__ void k_raypre(const float* __restrict__ ro, const float* __restrict__ rd,
                         const float* __restrict__ vd, const float* __restrict__ dw1,
                         const float* __restrict__ db1) {
    int r = blockIdx.x * blockDim.x + threadIdx.x;
    if (r >= NRAY) return;
    float ox = ro[3*r], oy = ro[3*r+1], oz = ro[3*r+2];
    float dx = rd[3*r], dy = rd[3*r+1], dz = rd[3*r+2];
    float vx = (dx == 0.f) ? 1e-6f : dx;
    float vy = (dy == 0.f) ? 1e-6f : dy;
    float vz = (dz == 0.f) ? 1e-6f : dz;
    float rax = (1.f - ox) / vx, rbx = (-1.f - ox) / vx;
    float ray_ = (1.f - oy) / vy, rby = (-1.f - oy) / vy;
    float raz = (1.f - oz) / vz, rbz = (-1.f - oz) / vz;
    float tmn = fmaxf(fmaxf(fminf(rax, rbx), fminf(ray_, rby)), fminf(raz, rbz));
    float tmx = fminf(fminf(fmaxf(rax, rbx), fmaxf(ray_, rby)), fmaxf(raz, rbz));
    tmn = fminf(fmaxf(tmn, NEARC), FARC);
    tmx = fminf(fmaxf(tmx, NEARC), FARC);
    float mask = (tmx <= tmn) ? 1.f : 0.f;
    float nn = sqrtf(dx*dx + dy*dy + dz*dz);
    g_rayinfo[4*r+0] = tmn;
    g_rayinfo[4*r+1] = nn;
    g_rayinfo[4*r+2] = mask;
    g_rayinfo[4*r+3] = 0.f;

    float wx = vd[3*r], wy = vd[3*r+1], wz = vd[3*r+2];
    float emb[39];
    emb[0] = wx; emb[1] = wy; emb[2] = wz;
    float f = 1.f;
#pragma unroll
    for (int l = 0; l < 6; l++) {
        emb[3+6*l+0] = sinf(wx*f); emb[3+6*l+1] = sinf(wy*f); emb[3+6*l+2] = sinf(wz*f);
        emb[3+6*l+3] = cosf(wx*f); emb[3+6*l+4] = cosf(wy*f); emb[3+6*l+5] = cosf(wz*f);
        f *= 2.f;
    }
#pragma unroll
    for (int j = 0; j < 16; j++) {
        float acc = db1[j];
#pragma unroll
        for (int k = 0; k < 39; k++) acc += emb[k] * dw1[(15+k)*16 + j];
        g_dbias[16*r + j] = acc;
    }
}

// =====================================================================
// Kernel 2: per-sample MLP evaluation -> scratch {alpha, rgb}
// one block (128 thr) per ray; attention MLP computed in 16-wide halves
// to keep true live state ~110 regs so (128,3)=170-reg cap doesn't spill
// =====================================================================
#define O_AW1 0
#define O_AB1 480
#define O_AW2 512
#define O_AB2 1536
#define O_AW3 1568
#define O_AB3 1696
#define O_PW1 1700
#define O_PB1 1892
#define O_PW2 1908
#define O_PB2 2164
#define O_PW3 2180
#define O_PB3 2436
#define O_DW1 2452
#define O_DW2 2692
#define O_DB2 2948
#define O_DW3 2964
#define O_DB3 3220
#define O_DW4 3236
#define O_DB4 3284
#define SW_TOT 3288

// packed layer chunk: IN inputs -> 2*OUTH outputs; weight rows have STRIDE
// floats (caller offsets base for column-halves). INIT=false accumulates.
template<int IN, int OUTH, int STRIDE, bool INIT>
__device__ __forceinline__ void layer2s(const float* __restrict__ x,
                                        const float* __restrict__ w,
                                        const float* __restrict__ b,
                                        u64* acc) {
    if (INIT) {
        const u64* b2 = reinterpret_cast<const u64*>(b);
#pragma unroll
        for (int j = 0; j < OUTH; j++) acc[j] = b2[j];
    }
#pragma unroll
    for (int i = 0; i < IN; i++) {
        u64 xb = pk2(x[i], x[i]);
        const ulonglong2* wr = reinterpret_cast<const ulonglong2*>(w + i * STRIDE);
#pragma unroll
        for (int j = 0; j < OUTH/2; j++) {
            ulonglong2 ww = wr[j];
            fma2(acc[2*j+0], xb, ww.x);
            fma2(acc[2*j+1], xb, ww.y);
        }
    }
}

template<int OUTH>
__device__ __forceinline__ void relu_unpack(const u64* acc, float* out) {
#pragma unroll
    for (int j = 0; j < OUTH; j++) {
        float a, b; upk2(acc[j], a, b);
        out[2*j]   = fmaxf(a, 0.f);
        out[2*j+1] = fmaxf(b, 0.f);
    }
}

__global__ __launch_bounds__(128, 3) void k_phaseA(
    const float* __restrict__ ro, const float* __restrict__ rd,
    const float* __restrict__ aw1, const float* __restrict__ ab1,
    const float* __restrict__ aw2, const float* __restrict__ ab2,
    const float* __restrict__ aw3, const float* __restrict__ ab3,
    const float* __restrict__ pw1, const float* __restrict__ pb1,
    const float* __restrict__ pw2, const float* __restrict__ pb2,
    const float* __restrict__ pw3, const float* __restrict__ pb3,
    const float* __restrict__ dw1,
    const float* __restrict__ dw2, const float* __restrict__ db2,
    const float* __restrict__ dw3, const float* __restrict__ db3,
    const float* __restrict__ dw4, const float* __restrict__ db4)
{
    __shared__ __align__(16) float sw[SW_TOT];
    __shared__ __align__(16) float s_db[16];
    __shared__ float s_ray[9];
    {
        int t = threadIdx.x;
        for (int i = t; i < 480;  i += 128) sw[O_AW1 + i] = aw1[i];
        for (int i = t; i < 32;   i += 128) sw[O_AB1 + i] = ab1[i];
        for (int i = t; i < 1024; i += 128) sw[O_AW2 + i] = aw2[i];
        for (int i = t; i < 32;   i += 128) sw[O_AB2 + i] = ab2[i];
        for (int i = t; i < 128;  i += 128) sw[O_AW3 + i] = aw3[i];
        for (int i = t; i < 4;    i += 128) sw[O_AB3 + i] = ab3[i];
        for (int i = t; i < 192;  i += 128) sw[O_PW1 + i] = pw1[i];
        for (int i = t; i < 16;   i += 128) sw[O_PB1 + i] = pb1[i];
        for (int i = t; i < 256;  i += 128) sw[O_PW2 + i] = pw2[i];
        for (int i = t; i < 16;   i += 128) sw[O_PB2 + i] = pb2[i];
        for (int i = t; i < 256;  i += 128) sw[O_PW3 + i] = pw3[i];
        for (int i = t; i < 16;   i += 128) sw[O_PB3 + i] = pb3[i];
        for (int i = t; i < 240;  i += 128) sw[O_DW1 + i] = dw1[i];  // rows 0..14
        for (int i = t; i < 256;  i += 128) sw[O_DW2 + i] = dw2[i];
        for (int i = t; i < 16;   i += 128) sw[O_DB2 + i] = db2[i];
        for (int i = t; i < 256;  i += 128) sw[O_DW3 + i] = dw3[i];
        for (int i = t; i < 16;   i += 128) sw[O_DB3 + i] = db3[i];
        for (int i = t; i < 48;   i += 128) sw[O_DW4 + i] = dw4[i];
        for (int i = t; i < 3;    i += 128) sw[O_DB4 + i] = db4[i];
        int ray0 = blockIdx.x;
        if (t < 16) s_db[t] = g_dbias[16*ray0 + t];
        if (t < 3)  s_ray[t] = g_rayinfo[4*ray0 + t];
        if (t >= 3 && t < 6) s_ray[t] = ro[3*ray0 + (t-3)];
        if (t >= 6 && t < 9) s_ray[t] = rd[3*ray0 + (t-6)];
    }
    __syncthreads();

    int ray = blockIdx.x;
    float tmn = s_ray[0], rn = s_ray[1], mask = s_ray[2];
    float rinv = STEPW / rn;
    float ox = s_ray[3], oy = s_ray[4], oz = s_ray[5];
    float ddx = s_ray[6], ddy = s_ray[7], ddz = s_ray[8];

    for (int s = threadIdx.x; s < NS; s += 128) {
        int oi = ray * NS + s;
        float it = tmn + rinv * (float)s;
        float px = ox + ddx * it;
        float py = oy + ddy * it;
        float pz = oz + ddz * it;
        bool inb = (mask == 0.f) &&
                   px >= -1.f && px <= 1.f &&
                   py >= -1.f && py <= 1.f &&
                   pz >= -1.f && pz <= 1.f;
        if (!inb) { g_scratch[oi] = make_float4(0.f, 0.f, 0.f, 0.f); continue; }

        // ---- trilinear from channel-last grid (packed accumulators) ----
        float gx = (px + 1.f) * 0.5f * 159.f;
        float gy = (py + 1.f) * 0.5f * 159.f;
        float gz = (pz + 1.f) * 0.5f * 159.f;
        float fx0 = floorf(gx), fy0 = floorf(gy), fz0 = floorf(gz);
        float wx1 = gx - fx0, wy1 = gy - fy0, wz1 = gz - fz0;
        float wx0 = 1.f - wx1, wy0 = 1.f - wy1, wz0 = 1.f - wz1;
        int ix0 = min(max((int)fx0, 0), 159); int ix1 = min(ix0 + 1, 159);
        int iy0 = min(max((int)fy0, 0), 159); int iy1 = min(iy0 + 1, 159);
        int iz0 = min(max((int)fz0, 0), 159); int iz1 = min(iz0 + 1, 159);

        u64 lat2[6];
#pragma unroll
        for (int k = 0; k < 6; k++) lat2[k] = 0ull;

#define ADD_CORNER(X, Y, Z, W) {                                                     \
            const ulonglong2* gp = reinterpret_cast<const ulonglong2*>(              \
                g_grid_t + (size_t)((((X)*160 + (Y))*160) + (Z)) * 12);              \
            ulonglong2 A = __ldg(gp), B = __ldg(gp+1), C = __ldg(gp+2);              \
            float W_ = (W);                                                          \
            u64 wb = pk2(W_, W_);                                                    \
            fma2(lat2[0], wb, A.x); fma2(lat2[1], wb, A.y);                          \
            fma2(lat2[2], wb, B.x); fma2(lat2[3], wb, B.y);                          \
            fma2(lat2[4], wb, C.x); fma2(lat2[5], wb, C.y); }

        ADD_CORNER(ix0, iy0, iz0, wx0*wy0*wz0);
        ADD_CORNER(ix0, iy0, iz1, wx0*wy0*wz1);
        ADD_CORNER(ix0, iy1, iz0, wx0*wy1*wz0);
        ADD_CORNER(ix0, iy1, iz1, wx0*wy1*wz1);
        ADD_CORNER(ix1, iy0, iz0, wx1*wy0*wz0);
        ADD_CORNER(ix1, iy0, iz1, wx1*wy0*wz1);
        ADD_CORNER(ix1, iy1, iz0, wx1*wy1*wz0);
        ADD_CORNER(ix1, iy1, iz1, wx1*wy1*wz1);
#undef ADD_CORNER

        float lat[12];
#pragma unroll
        for (int k = 0; k < 6; k++) upk2(lat2[k], lat[2*k], lat[2*k+1]);

        float crd[3];
        crd[0] = pz; crd[1] = py; crd[2] = px;

        // ---- attention MLP in 16-wide halves: 15 -> 32 -> 32 -> 4 ----
        u64 acc8[8];
        float h1[32];
        // layer1, cols [0,16): coords rows 0..2, lat rows 3..14
        layer2s<3, 8, 32, true >(crd, &sw[O_AW1 + 0],       &sw[O_AB1 + 0],  acc8);
        layer2s<12, 8, 32, false>(lat, &sw[O_AW1 + 3*32 + 0], (const float*)0, acc8);
        relu_unpack<8>(acc8, &h1[0]);
        // layer1, cols [16,32)
        layer2s<3, 8, 32, true >(crd, &sw[O_AW1 + 16],       &sw[O_AB1 + 16], acc8);
        layer2s<12, 8, 32, false>(lat, &sw[O_AW1 + 3*32 + 16], (const float*)0, acc8);
        relu_unpack<8>(acc8, &h1[16]);

        float h2[32];
        // layer2, cols [0,16)
        layer2s<32, 8, 32, true>(h1, &sw[O_AW2 + 0],  &sw[O_AB2 + 0],  acc8);
        relu_unpack<8>(acc8, &h2[0]);
        // layer2, cols [16,32)
        layer2s<32, 8, 32, true>(h1, &sw[O_AW2 + 16], &sw[O_AB2 + 16], acc8);
        relu_unpack<8>(acc8, &h2[16]);

        // layer3: 32 -> 4
        u64 accO[2];
        layer2s<32, 2, 4, true>(h2, &sw[O_AW3], &sw[O_AB3], accO);
        float o0, o1, o2, o3;
        upk2(accO[0], o0, o1); upk2(accO[1], o2, o3);
        float mx = fmaxf(fmaxf(o0, o1), fmaxf(o2, o3));
        float e0 = expf(o0-mx), e1 = expf(o1-mx), e2 = expf(o2-mx), e3 = expf(o3-mx);
        float att1 = e1 / (e0 + e1 + e2 + e3);

        // ---- pos MLP: lat (12) -> 16 -> 16 -> 16 ----
        float p1[16], p2[16], p3[16];
        layer2s<12, 8, 16, true>(lat, &sw[O_PW1], &sw[O_PB1], acc8);
        relu_unpack<8>(acc8, p1);
        layer2s<16, 8, 16, true>(p1, &sw[O_PW2], &sw[O_PB2], acc8);
        relu_unpack<8>(acc8, p2);
        layer2s<16, 8, 16, true>(p2, &sw[O_PW3], &sw[O_PB3], acc8);
#pragma unroll
        for (int j = 0; j < 8; j++) upk2(acc8[j], p3[2*j], p3[2*j+1]);  // no relu

        // ---- dir MLP: [p3[1:16] ; emb(folded bias)] -> 16 -> 16 -> 16 -> 3 ----
        float d1[16], d2[16], d3[16];
        layer2s<15, 8, 16, true>(&p3[1], &sw[O_DW1], s_db, acc8);
        relu_unpack<8>(acc8, d1);
        layer2s<16, 8, 16, true>(d1, &sw[O_DW2], &sw[O_DB2], acc8);
        relu_unpack<8>(acc8, d2);
        layer2s<16, 8, 16, true>(d2, &sw[O_DW3], &sw[O_DB3], acc8);
        relu_unpack<8>(acc8, d3);

        float r0 = sw[O_DB4+0], r1 = sw[O_DB4+1], r2 = sw[O_DB4+2];
#pragma unroll
        for (int i = 0; i < 16; i++) {
            float xi = d3[i];
            r0 += xi * sw[O_DW4 + i*3 + 0];
            r1 += xi * sw[O_DW4 + i*3 + 1];
            r2 += xi * sw[O_DW4 + i*3 + 2];
        }

        // ---- activations ----
        float dens = att1 * p3[0];
        float xs = dens + ACT_SHIFT;
        float sp = fmaxf(xs, 0.f) + log1pf(expf(-fabsf(xs)));   // softplus
        float alpha = 1.f - expf(-sp * 0.5f);
        float c0 = 1.f / (1.f + expf(-att1 * r0));
        float c1 = 1.f / (1.f + expf(-att1 * r1));
        float c2 = 1.f / (1.f + expf(-att1 * r2));

        g_scratch[oi] = make_float4(alpha, c0, c1, c2);
    }
}

// =====================================================================
// Kernel 3: warp-per-ray alpha compositing (shfl prefix-product scan)
// =====================================================================
__global__ __launch_bounds__(256) void k_phaseB(float* __restrict__ out) {
    int gid  = blockIdx.x * blockDim.x + threadIdx.x;
    int ray  = gid >> 5;
    int lane = gid & 31;
    if (ray >= NRAY) return;

    float tmn = g_rayinfo[4*ray], rn = g_rayinfo[4*ray+1];
    float base_depth = tmn * rn;

    float T = 1.f;
    float sr = 0.f, sg = 0.f, sb = 0.f, sd = 0.f, sa = 0.f;

    for (int c0 = 0; c0 < NS; c0 += 32) {
        int s = c0 + lane;
        float4 rec = make_float4(0.f, 0.f, 0.f, 0.f);
        if (s < NS) rec = g_scratch[ray*NS + s];
        float a = rec.x;
        float q = fmaxf(1.f - a, 1e-10f);
        float ip = q;
#pragma unroll
        for (int off = 1; off < 32; off <<= 1) {
            float v = __shfl_up_sync(0xFFFFFFFFu, ip, off);
            if (lane >= off) ip *= v;
        }
        float ep = __shfl_up_sync(0xFFFFFFFFu, ip, 1);
        if (lane == 0) ep = 1.f;
        float w = a * T * ep;
        sr += w * rec.y;
        sg += w * rec.z;
        sb += w * rec.w;
        sd += w * (base_depth + STEPW * (float)s);
        sa += w;
        T *= __shfl_sync(0xFFFFFFFFu, ip, 31);
    }

#pragma unroll
    for (int off = 16; off > 0; off >>= 1) {
        sr += __shfl_xor_sync(0xFFFFFFFFu, sr, off);
        sg += __shfl_xor_sync(0xFFFFFFFFu, sg, off);
        sb += __shfl_xor_sync(0xFFFFFFFFu, sb, off);
        sd += __shfl_xor_sync(0xFFFFFFFFu, sd, off);
        sa += __shfl_xor_sync(0xFFFFFFFFu, sa, off);
    }

    if (lane == 0) {
        float depth = sd + T * FARC;
        out[ray*6+0] = sr + T * BGC;
        out[ray*6+1] = sg + T * BGC;
        out[ray*6+2] = sb + T * BGC;
        out[ray*6+3] = depth;
        out[ray*6+4] = 1.f / depth;
        out[ray*6+5] = sa;
    }
}

// =====================================================================
extern "C" void kernel_launch(void* const* d_in, const int* in_sizes, int n_in,
                              void* d_out, int out_size) {
    const float* ro  = (const float*)d_in[0];
    const float* rd  = (const float*)d_in[1];
    const float* vd  = (const float*)d_in[2];
    const float* grd = (const float*)d_in[3];
    const float* aw1 = (const float*)d_in[4];
    const float* ab1 = (const float*)d_in[5];
    const float* aw2 = (const float*)d_in[6];
    const float* ab2 = (const float*)d_in[7];
    const float* aw3 = (const float*)d_in[8];
    const float* ab3 = (const float*)d_in[9];
    const float* pw1 = (const float*)d_in[10];
    const float* pb1 = (const float*)d_in[11];
    const float* pw2 = (const float*)d_in[12];
    const float* pb2 = (const float*)d_in[13];
    const float* pw3 = (const float*)d_in[14];
    const float* pb3 = (const float*)d_in[15];
    const float* dw1 = (const float*)d_in[16];
    const float* db1 = (const float*)d_in[17];
    const float* dw2 = (const float*)d_in[18];
    const float* db2 = (const float*)d_in[19];
    const float* dw3 = (const float*)d_in[20];
    const float* db3 = (const float*)d_in[21];
    const float* dw4 = (const float*)d_in[22];
    const float* db4 = (const float*)d_in[23];

    k_transpose<<<(R3/4 + 255) / 256, 256>>>(grd);
    k_raypre<<<(NRAY + 255) / 256, 256>>>(ro, rd, vd, dw1, db1);
    k_phaseA<<<NRAY, 128>>>(ro, rd,
                            aw1, ab1, aw2, ab2, aw3, ab3,
                            pw1, pb1, pw2, pb2, pw3, pb3,
                            dw1, dw2, db2, dw3, db3, dw4, db4);
    k_phaseB<<<(NRAY * 32) / 256, 256>>>((float*)d_out);
}

// round 13
// speedup vs baseline: 1.0923x; 1.0037x over previous
#include <cuda_runtime.h>
#include <math.h>

#define RES   160
#define R3    (RES*RES*RES)
#define NRAY  2048
#define NS    558
#define NEARC 0.05f
#define FARC  3.5f
#define BGC   1.0f
#define STEPW 0.00625f                 /* STEPSIZE * VOXEL = 0.5 * 0.0125 */
#define ACT_SHIFT -4.5951198501345898f /* log(1/(1-0.01)-1) */

typedef unsigned long long u64;

// ---- packed f32x2 helpers (Blackwell-only; ptxas never auto-fuses FFMA2) ----
__device__ __forceinline__ u64 pk2(float lo, float hi) {
    u64 r; asm("mov.b64 %0, {%1, %2};" : "=l"(r) : "f"(lo), "f"(hi)); return r;
}
__device__ __forceinline__ void upk2(u64 v, float& lo, float& hi) {
    asm("mov.b64 {%0, %1}, %2;" : "=f"(lo), "=f"(hi) : "l"(v));
}
__device__ __forceinline__ void fma2(u64& d, u64 a, u64 b) {
    asm("fma.rn.f32x2 %0, %1, %2, %0;" : "+l"(d) : "l"(a), "l"(b));
}

// ---- device scratch (static; no allocations allowed) ----
__device__ float  g_grid_t[(size_t)R3 * 12];   // channel-last grid, 196.6 MB
__device__ float4 g_scratch[NRAY * NS];        // {alpha, r, g, b} per sample
__device__ float  g_rayinfo[NRAY * 4];         // tmin, |d|, mask, pad
__device__ float  g_dbias[NRAY * 16];          // per-ray dir-layer1 bias (emb folded)

// =====================================================================
// Kernel 0: transpose grid (C,R,R,R) -> (R,R,R,C); 4 voxels per thread
// =====================================================================
__global__ __launch_bounds__(256) void k_transpose(const float* __restrict__ g) {
    int v4 = blockIdx.x * blockDim.x + threadIdx.x;
    if (v4 >= R3/4) return;
    size_t v = (size_t)v4 * 4;
    float4 a[12];
#pragma unroll
    for (int c = 0; c < 12; c++)
        a[c] = __ldg(reinterpret_cast<const float4*>(g + (size_t)c * R3 + v));
    float4* dst = reinterpret_cast<float4*>(g_grid_t + v * 12);
#pragma unroll
    for (int k = 0; k < 4; k++) {
        float vals[12];
#pragma unroll
        for (int c = 0; c < 12; c++)
            vals[c] = (k == 0) ? a[c].x : (k == 1) ? a[c].y : (k == 2) ? a[c].z : a[c].w;
        dst[k*3+0] = make_float4(vals[0], vals[1], vals[2],  vals[3]);
        dst[k*3+1] = make_float4(vals[4], vals[5], vals[6],  vals[7]);
        dst[k*3+2] = make_float4(vals[8], vals[9], vals[10], vals[11]);
    }
}

// =====================================================================
// Kernel 1: per-ray precompute (tmin, |d|, mask, dir-layer1 bias)
// =====================================================================
__global__ void k_raypre(const float* __restrict__ ro, const float* __restrict__ rd,
                         const float* __restrict__ vd, const float* __restrict__ dw1,
                         const float* __restrict__ db1) {
    int r = blockIdx.x * blockDim.x + threadIdx.x;
    if (r >= NRAY) return;
    float ox = ro[3*r], oy = ro[3*r+1], oz = ro[3*r+2];
    float dx = rd[3*r], dy = rd[3*r+1], dz = rd[3*r+2];
    float vx = (dx == 0.f) ? 1e-6f : dx;
    float vy = (dy == 0.f) ? 1e-6f : dy;
    float vz = (dz == 0.f) ? 1e-6f : dz;
    float rax = (1.f - ox) / vx, rbx = (-1.f - ox) / vx;
    float ray_ = (1.f - oy) / vy, rby = (-1.f - oy) / vy;
    float raz = (1.f - oz) / vz, rbz = (-1.f - oz) / vz;
    float tmn = fmaxf(fmaxf(fminf(rax, rbx), fminf(ray_, rby)), fminf(raz, rbz));
    float tmx = fminf(fminf(fmaxf(rax, rbx), fmaxf(ray_, rby)), fmaxf(raz, rbz));
    tmn = fminf(fmaxf(tmn, NEARC), FARC);
    tmx = fminf(fmaxf(tmx, NEARC), FARC);
    float mask = (tmx <= tmn) ? 1.f : 0.f;
    float nn = sqrtf(dx*dx + dy*dy + dz*dz);
    g_rayinfo[4*r+0] = tmn;
    g_rayinfo[4*r+1] = nn;
    g_rayinfo[4*r+2] = mask;
    g_rayinfo[4*r+3] = 0.f;

    // positional encoding of viewdir (per-ray constant) folded into dir bias
    float wx = vd[3*r], wy = vd[3*r+1], wz = vd[3*r+2];
    float emb[39];
    emb[0] = wx; emb[1] = wy; emb[2] = wz;
    float f = 1.f;
#pragma unroll
    for (int l = 0; l < 6; l++) {
        emb[3+6*l+0] = sinf(wx*f); emb[3+6*l+1] = sinf(wy*f); emb[3+6*l+2] = sinf(wz*f);
        emb[3+6*l+3] = cosf(wx*f); emb[3+6*l+4] = cosf(wy*f); emb[3+6*l+5] = cosf(wz*f);
        f *= 2.f;
    }
#pragma unroll
    for (int j = 0; j < 16; j++) {
        float acc = db1[j];
#pragma unroll
        for (int k = 0; k < 39; k++) acc += emb[k] * dw1[(15+k)*16 + j];
        g_dbias[16*r + j] = acc;
    }
}

// =====================================================================
// Kernel 2: per-sample MLP evaluation -> scratch {alpha, rgb}
// grid: (ceil(NS/256), NRAY); one block serves one ray's sample chunk
// (EXACT R3 codegen — measured 205.3us total; do not touch)
// =====================================================================
#define O_AW1 0
#define O_AB1 480
#define O_AW2 512
#define O_AB2 1536
#define O_AW3 1568
#define O_AB3 1696
#define O_PW1 1700
#define O_PB1 1892
#define O_PW2 1908
#define O_PB2 2164
#define O_PW3 2180
#define O_PB3 2436
#define O_DW1 2452
#define O_DW2 2692
#define O_DB2 2948
#define O_DW3 2964
#define O_DB3 3220
#define O_DW4 3236
#define O_DB4 3284
#define SW_TOT 3288

// packed layer: IN scalar inputs -> OUT (=2*OUTH) packed accumulators
template<int IN, int OUTH>
__device__ __forceinline__ void layer2(const float* __restrict__ x,
                                       const float* __restrict__ sw_w,
                                       const float* __restrict__ sw_b,
                                       u64* acc) {
    const u64* b2 = reinterpret_cast<const u64*>(sw_b);
#pragma unroll
    for (int j = 0; j < OUTH; j++) acc[j] = b2[j];
#pragma unroll
    for (int i = 0; i < IN; i++) {
        u64 xb = pk2(x[i], x[i]);
        const ulonglong2* w = reinterpret_cast<const ulonglong2*>(sw_w + i * (2*OUTH));
#pragma unroll
        for (int j = 0; j < OUTH/2; j++) {
            ulonglong2 ww = w[j];
            fma2(acc[2*j+0], xb, ww.x);
            fma2(acc[2*j+1], xb, ww.y);
        }
    }
}

template<int OUTH>
__device__ __forceinline__ void relu_unpack(const u64* acc, float* out) {
#pragma unroll
    for (int j = 0; j < OUTH; j++) {
        float a, b; upk2(acc[j], a, b);
        out[2*j]   = fmaxf(a, 0.f);
        out[2*j+1] = fmaxf(b, 0.f);
    }
}

__global__ __launch_bounds__(256) void k_phaseA(
    const float* __restrict__ ro, const float* __restrict__ rd,
    const float* __restrict__ aw1, const float* __restrict__ ab1,
    const float* __restrict__ aw2, const float* __restrict__ ab2,
    const float* __restrict__ aw3, const float* __restrict__ ab3,
    const float* __restrict__ pw1, const float* __restrict__ pb1,
    const float* __restrict__ pw2, const float* __restrict__ pb2,
    const float* __restrict__ pw3, const float* __restrict__ pb3,
    const float* __restrict__ dw1,
    const float* __restrict__ dw2, const float* __restrict__ db2,
    const float* __restrict__ dw3, const float* __restrict__ db3,
    const float* __restrict__ dw4, const float* __restrict__ db4)
{
    __shared__ float sw[SW_TOT];
    __shared__ float s_db[16];
    __shared__ float s_ray[9];   // tmin, |d|, mask, ox,oy,oz, dx,dy,dz
    {
        int t = threadIdx.x;
        for (int i = t; i < 480;  i += 256) sw[O_AW1 + i] = aw1[i];
        for (int i = t; i < 32;   i += 256) sw[O_AB1 + i] = ab1[i];
        for (int i = t; i < 1024; i += 256) sw[O_AW2 + i] = aw2[i];
        for (int i = t; i < 32;   i += 256) sw[O_AB2 + i] = ab2[i];
        for (int i = t; i < 128;  i += 256) sw[O_AW3 + i] = aw3[i];
        for (int i = t; i < 4;    i += 256) sw[O_AB3 + i] = ab3[i];
        for (int i = t; i < 192;  i += 256) sw[O_PW1 + i] = pw1[i];
        for (int i = t; i < 16;   i += 256) sw[O_PB1 + i] = pb1[i];
        for (int i = t; i < 256;  i += 256) sw[O_PW2 + i] = pw2[i];
        for (int i = t; i < 16;   i += 256) sw[O_PB2 + i] = pb2[i];
        for (int i = t; i < 256;  i += 256) sw[O_PW3 + i] = pw3[i];
        for (int i = t; i < 16;   i += 256) sw[O_PB3 + i] = pb3[i];
        for (int i = t; i < 240;  i += 256) sw[O_DW1 + i] = dw1[i];  // rows 0..14 only
        for (int i = t; i < 256;  i += 256) sw[O_DW2 + i] = dw2[i];
        for (int i = t; i < 16;   i += 256) sw[O_DB2 + i] = db2[i];
        for (int i = t; i < 256;  i += 256) sw[O_DW3 + i] = dw3[i];
        for (int i = t; i < 16;   i += 256) sw[O_DB3 + i] = db3[i];
        for (int i = t; i < 48;   i += 256) sw[O_DW4 + i] = dw4[i];
        for (int i = t; i < 3;    i += 256) sw[O_DB4 + i] = db4[i];
        int ray0 = blockIdx.y;
        if (t < 16) s_db[t] = g_dbias[16*ray0 + t];
        if (t < 3)  s_ray[t] = g_rayinfo[4*ray0 + t];
        if (t >= 3 && t < 6) s_ray[t] = ro[3*ray0 + (t-3)];
        if (t >= 6 && t < 9) s_ray[t] = rd[3*ray0 + (t-6)];
    }
    __syncthreads();

    int ray = blockIdx.y;
    int s = blockIdx.x * 256 + threadIdx.x;
    if (s >= NS) return;
    int oi = ray * NS + s;

    float tmn = s_ray[0], rn = s_ray[1], mask = s_ray[2];
    float it = tmn + STEPW * (float)s / rn;
    float px = s_ray[3] + s_ray[6] * it;
    float py = s_ray[4] + s_ray[7] * it;
    float pz = s_ray[5] + s_ray[8] * it;
    bool inb = (mask == 0.f) &&
               px >= -1.f && px <= 1.f &&
               py >= -1.f && py <= 1.f &&
               pz >= -1.f && pz <= 1.f;
    if (!inb) { g_scratch[oi] = make_float4(0.f, 0.f, 0.f, 0.f); return; }

    // ---- trilinear from channel-last grid (packed accumulators) ----
    float gx = (px + 1.f) * 0.5f * 159.f;
    float gy = (py + 1.f) * 0.5f * 159.f;
    float gz = (pz + 1.f) * 0.5f * 159.f;
    float fx0 = floorf(gx), fy0 = floorf(gy), fz0 = floorf(gz);
    float wx1 = gx - fx0, wy1 = gy - fy0, wz1 = gz - fz0;
    float wx0 = 1.f - wx1, wy0 = 1.f - wy1, wz0 = 1.f - wz1;
    int ix0 = min(max((int)fx0, 0), 159); int ix1 = min(ix0 + 1, 159);
    int iy0 = min(max((int)fy0, 0), 159); int iy1 = min(iy0 + 1, 159);
    int iz0 = min(max((int)fz0, 0), 159); int iz1 = min(iz0 + 1, 159);

    u64 lat2[6];
#pragma unroll
    for (int k = 0; k < 6; k++) lat2[k] = 0ull;

#define ADD_CORNER(X, Y, Z, W) {                                                     \
        const ulonglong2* gp = reinterpret_cast<const ulonglong2*>(                  \
            g_grid_t + (size_t)((((X)*160 + (Y))*160) + (Z)) * 12);                  \
        ulonglong2 A = __ldg(gp), B = __ldg(gp+1), C = __ldg(gp+2);                  \
        float W_ = (W);                                                              \
        u64 wb = pk2(W_, W_);                                                        \
        fma2(lat2[0], wb, A.x); fma2(lat2[1], wb, A.y);                              \
        fma2(lat2[2], wb, B.x); fma2(lat2[3], wb, B.y);                              \
        fma2(lat2[4], wb, C.x); fma2(lat2[5], wb, C.y); }

    ADD_CORNER(ix0, iy0, iz0, wx0*wy0*wz0);
    ADD_CORNER(ix0, iy0, iz1, wx0*wy0*wz1);
    ADD_CORNER(ix0, iy1, iz0, wx0*wy1*wz0);
    ADD_CORNER(ix0, iy1, iz1, wx0*wy1*wz1);
    ADD_CORNER(ix1, iy0, iz0, wx1*wy0*wz0);
    ADD_CORNER(ix1, iy0, iz1, wx1*wy0*wz1);
    ADD_CORNER(ix1, iy1, iz0, wx1*wy1*wz0);
    ADD_CORNER(ix1, iy1, iz1, wx1*wy1*wz1);
#undef ADD_CORNER

    float lat[12];
#pragma unroll
    for (int k = 0; k < 6; k++) upk2(lat2[k], lat[2*k], lat[2*k+1]);

    // ---- attention MLP: [pz,py,px, lat] (15) -> 32 -> 32 -> 4 -> softmax[1]
    float xin[15];
    xin[0] = pz; xin[1] = py; xin[2] = px;
#pragma unroll
    for (int k = 0; k < 12; k++) xin[3+k] = lat[k];

    u64 acc16[16];
    float h1[32], h2[32];
    layer2<15, 16>(xin, &sw[O_AW1], &sw[O_AB1], acc16);
    relu_unpack<16>(acc16, h1);
    layer2<32, 16>(h1, &sw[O_AW2], &sw[O_AB2], acc16);
    relu_unpack<16>(acc16, h2);

    u64 accO[2];
    layer2<32, 2>(h2, &sw[O_AW3], &sw[O_AB3], accO);
    float o0, o1, o2, o3;
    upk2(accO[0], o0, o1); upk2(accO[1], o2, o3);
    float mx = fmaxf(fmaxf(o0, o1), fmaxf(o2, o3));
    float e0 = expf(o0-mx), e1 = expf(o1-mx), e2 = expf(o2-mx), e3 = expf(o3-mx);
    float att1 = e1 / (e0 + e1 + e2 + e3);

    // ---- pos MLP: lat (12) -> 16 -> 16 -> 16 ----
    u64 acc8[8];
    float p1[16], p2[16], p3[16];
    layer2<12, 8>(lat, &sw[O_PW1], &sw[O_PB1], acc8);
    relu_unpack<8>(acc8, p1);
    layer2<16, 8>(p1, &sw[O_PW2], &sw[O_PB2], acc8);
    relu_unpack<8>(acc8, p2);
    layer2<16, 8>(p2, &sw[O_PW3], &sw[O_PB3], acc8);
#pragma unroll
    for (int j = 0; j < 8; j++) upk2(acc8[j], p3[2*j], p3[2*j+1]);  // no relu

    // ---- dir MLP: [p3[1:16] ; emb(folded bias)] -> 16 -> 16 -> 16 -> 3 ----
    float d1[16], d2[16], d3[16];
    layer2<15, 8>(&p3[1], &sw[O_DW1], s_db, acc8);
    relu_unpack<8>(acc8, d1);
    layer2<16, 8>(d1, &sw[O_DW2], &sw[O_DB2], acc8);
    relu_unpack<8>(acc8, d2);
    layer2<16, 8>(d2, &sw[O_DW3], &sw[O_DB3], acc8);
    relu_unpack<8>(acc8, d3);

    float r0 = sw[O_DB4+0], r1 = sw[O_DB4+1], r2 = sw[O_DB4+2];
#pragma unroll
    for (int i = 0; i < 16; i++) {
        float xi = d3[i];
        r0 += xi * sw[O_DW4 + i*3 + 0];
        r1 += xi * sw[O_DW4 + i*3 + 1];
        r2 += xi * sw[O_DW4 + i*3 + 2];
    }

    // ---- activations ----
    float dens = att1 * p3[0];
    float xs = dens + ACT_SHIFT;
    float sp = fmaxf(xs, 0.f) + log1pf(expf(-fabsf(xs)));   // softplus
    float alpha = 1.f - expf(-sp * 0.5f);
    float c0 = 1.f / (1.f + expf(-att1 * r0));
    float c1 = 1.f / (1.f + expf(-att1 * r1));
    float c2 = 1.f / (1.f + expf(-att1 * r2));

    g_scratch[oi] = make_float4(alpha, c0, c1, c2);
}

// =====================================================================
// Kernel 3: warp-per-ray alpha compositing (shfl prefix-product scan)
// =====================================================================
__global__ __launch_bounds__(256) void k_phaseB(float* __restrict__ out) {
    int gid  = blockIdx.x * blockDim.x + threadIdx.x;
    int ray  = gid >> 5;
    int lane = gid & 31;
    if (ray >= NRAY) return;

    float tmn = g_rayinfo[4*ray], rn = g_rayinfo[4*ray+1];
    float base_depth = tmn * rn;

    float T = 1.f;
    float sr = 0.f, sg = 0.f, sb = 0.f, sd = 0.f, sa = 0.f;

    for (int c0 = 0; c0 < NS; c0 += 32) {
        int s = c0 + lane;
        float4 rec = make_float4(0.f, 0.f, 0.f, 0.f);
        if (s < NS) rec = g_scratch[ray*NS + s];
        float a = rec.x;
        float q = fmaxf(1.f - a, 1e-10f);
        float ip = q;
#pragma unroll
        for (int off = 1; off < 32; off <<= 1) {
            float v = __shfl_up_sync(0xFFFFFFFFu, ip, off);
            if (lane >= off) ip *= v;
        }
        float ep = __shfl_up_sync(0xFFFFFFFFu, ip, 1);
        if (lane == 0) ep = 1.f;
        float w = a * T * ep;
        sr += w * rec.y;
        sg += w * rec.z;
        sb += w * rec.w;
        sd += w * (base_depth + STEPW * (float)s);
        sa += w;
        T *= __shfl_sync(0xFFFFFFFFu, ip, 31);
    }

#pragma unroll
    for (int off = 16; off > 0; off >>= 1) {
        sr += __shfl_xor_sync(0xFFFFFFFFu, sr, off);
        sg += __shfl_xor_sync(0xFFFFFFFFu, sg, off);
        sb += __shfl_xor_sync(0xFFFFFFFFu, sb, off);
        sd += __shfl_xor_sync(0xFFFFFFFFu, sd, off);
        sa += __shfl_xor_sync(0xFFFFFFFFu, sa, off);
    }

    if (lane == 0) {
        float depth = sd + T * FARC;
        out[ray*6+0] = sr + T * BGC;
        out[ray*6+1] = sg + T * BGC;
        out[ray*6+2] = sb + T * BGC;
        out[ray*6+3] = depth;
        out[ray*6+4] = 1.f / depth;
        out[ray*6+5] = sa;
    }
}

// =====================================================================
extern "C" void kernel_launch(void* const* d_in, const int* in_sizes, int n_in,
                              void* d_out, int out_size) {
    const float* ro  = (const float*)d_in[0];
    const float* rd  = (const float*)d_in[1];
    const float* vd  = (const float*)d_in[2];
    const float* grd = (const float*)d_in[3];
    const float* aw1 = (const float*)d_in[4];
    const float* ab1 = (const float*)d_in[5];
    const float* aw2 = (const float*)d_in[6];
    const float* ab2 = (const float*)d_in[7];
    const float* aw3 = (const float*)d_in[8];
    const float* ab3 = (const float*)d_in[9];
    const float* pw1 = (const float*)d_in[10];
    const float* pb1 = (const float*)d_in[11];
    const float* pw2 = (const float*)d_in[12];
    const float* pb2 = (const float*)d_in[13];
    const float* pw3 = (const float*)d_in[14];
    const float* pb3 = (const float*)d_in[15];
    const float* dw1 = (const float*)d_in[16];
    const float* db1 = (const float*)d_in[17];
    const float* dw2 = (const float*)d_in[18];
    const float* db2 = (const float*)d_in[19];
    const float* dw3 = (const float*)d_in[20];
    const float* db3 = (const float*)d_in[21];
    const float* dw4 = (const float*)d_in[22];
    const float* db4 = (const float*)d_in[23];

    k_transpose<<<(R3/4 + 255) / 256, 256>>>(grd);
    k_raypre<<<(NRAY + 255) / 256, 256>>>(ro, rd, vd, dw1, db1);
    dim3 gA((NS + 255) / 256, NRAY);
    k_phaseA<<<gA, 256>>>(ro, rd,
                          aw1, ab1, aw2, ab2, aw3, ab3,
                          pw1, pb1, pw2, pb2, pw3, pb3,
                          dw1, dw2, db2, dw3, db3, dw4, db4);
    k_phaseB<<<(NRAY * 32) / 256, 256>>>((float*)d_out);
}

// round 14
// speedup vs baseline: 1.5789x; 1.4455x over previous
#include <cuda_runtime.h>
#include <math.h>

#define RES   160
#define R3    (RES*RES*RES)
#define NRAY  2048
#define NS    558
#define NEARC 0.05f
#define FARC  3.5f
#define BGC   1.0f
#define STEPW 0.00625f                 /* STEPSIZE * VOXEL = 0.5 * 0.0125 */
#define ACT_SHIFT -4.5951198501345898f /* log(1/(1-0.01)-1) */

typedef unsigned long long u64;

// ---- packed f32x2 helpers (Blackwell-only; ptxas never auto-fuses FFMA2) ----
__device__ __forceinline__ u64 pk2(float lo, float hi) {
    u64 r; asm("mov.b64 %0, {%1, %2};" : "=l"(r) : "f"(lo), "f"(hi)); return r;
}
__device__ __forceinline__ void upk2(u64 v, float& lo, float& hi) {
    asm("mov.b64 {%0, %1}, %2;" : "=f"(lo), "=f"(hi) : "l"(v));
}
__device__ __forceinline__ void fma2(u64& d, u64 a, u64 b) {
    asm("fma.rn.f32x2 %0, %1, %2, %0;" : "+l"(d) : "l"(a), "l"(b));
}

// ---- device scratch (static; no allocations allowed) ----
__device__ float  g_grid_t[(size_t)R3 * 12];   // channel-last grid, 196.6 MB
__device__ float4 g_scratch[NRAY * NS];        // {alpha, r, g, b} per sample
__device__ float  g_rayinfo[NRAY * 4];         // tmin, |d|, mask, pad
__device__ float  g_dbias[NRAY * 16];          // per-ray dir-layer1 bias (emb folded)

// =====================================================================
// Kernel 0: transpose grid (C,R,R,R) -> (R,R,R,C)
// smem-staged: coalesced LDG (lane-stride 4B) AND coalesced STG.128
// =====================================================================
__global__ __launch_bounds__(256) void k_transpose(const float* __restrict__ g) {
    __shared__ __align__(16) float tile[256 * 12];   // 12 KB
    int v0 = blockIdx.x * 256;
    int t  = threadIdx.x;
    int v  = v0 + t;                                  // R3 % 256 == 0
#pragma unroll
    for (int c = 0; c < 12; c++)
        tile[t * 12 + c] = __ldg(g + (size_t)c * R3 + v);
    __syncthreads();
    float4* dst = reinterpret_cast<float4*>(g_grid_t + (size_t)v0 * 12);
    const float4* src = reinterpret_cast<const float4*>(tile);
#pragma unroll
    for (int i = 0; i < 3; i++)
        dst[i * 256 + t] = src[i * 256 + t];
}

// =====================================================================
// Kernel 1: per-ray precompute (tmin, |d|, mask, dir-layer1 bias)
// =====================================================================
__global__ void k_raypre(const float* __restrict__ ro, const float* __restrict__ rd,
                         const float* __restrict__ vd, const float* __restrict__ dw1,
                         const float* __restrict__ db1) {
    int r = blockIdx.x * blockDim.x + threadIdx.x;
    if (r >= NRAY) return;
    float ox = ro[3*r], oy = ro[3*r+1], oz = ro[3*r+2];
    float dx = rd[3*r], dy = rd[3*r+1], dz = rd[3*r+2];
    float vx = (dx == 0.f) ? 1e-6f : dx;
    float vy = (dy == 0.f) ? 1e-6f : dy;
    float vz = (dz == 0.f) ? 1e-6f : dz;
    float rax = (1.f - ox) / vx, rbx = (-1.f - ox) / vx;
    float ray_ = (1.f - oy) / vy, rby = (-1.f - oy) / vy;
    float raz = (1.f - oz) / vz, rbz = (-1.f - oz) / vz;
    float tmn = fmaxf(fmaxf(fminf(rax, rbx), fminf(ray_, rby)), fminf(raz, rbz));
    float tmx = fminf(fminf(fmaxf(rax, rbx), fmaxf(ray_, rby)), fmaxf(raz, rbz));
    tmn = fminf(fmaxf(tmn, NEARC), FARC);
    tmx = fminf(fmaxf(tmx, NEARC), FARC);
    float mask = (tmx <= tmn) ? 1.f : 0.f;
    float nn = sqrtf(dx*dx + dy*dy + dz*dz);
    g_rayinfo[4*r+0] = tmn;
    g_rayinfo[4*r+1] = nn;
    g_rayinfo[4*r+2] = mask;
    g_rayinfo[4*r+3] = 0.f;

    // positional encoding of viewdir (per-ray constant) folded into dir bias
    float wx = vd[3*r], wy = vd[3*r+1], wz = vd[3*r+2];
    float emb[39];
    emb[0] = wx; emb[1] = wy; emb[2] = wz;
    float f = 1.f;
#pragma unroll
    for (int l = 0; l < 6; l++) {
        emb[3+6*l+0] = sinf(wx*f); emb[3+6*l+1] = sinf(wy*f); emb[3+6*l+2] = sinf(wz*f);
        emb[3+6*l+3] = cosf(wx*f); emb[3+6*l+4] = cosf(wy*f); emb[3+6*l+5] = cosf(wz*f);
        f *= 2.f;
    }
#pragma unroll
    for (int j = 0; j < 16; j++) {
        float acc = db1[j];
#pragma unroll
        for (int k = 0; k < 39; k++) acc += emb[k] * dw1[(15+k)*16 + j];
        g_dbias[16*r + j] = acc;
    }
}

// =====================================================================
// Kernel 2: per-sample MLP evaluation -> scratch {alpha, rgb}
// grid: (ceil(NS/256), NRAY); one block serves one ray's sample chunk
// (EXACT R3 codegen — measured as part of the 205.3us build; do not touch)
// =====================================================================
#define O_AW1 0
#define O_AB1 480
#define O_AW2 512
#define O_AB2 1536
#define O_AW3 1568
#define O_AB3 1696
#define O_PW1 1700
#define O_PB1 1892
#define O_PW2 1908
#define O_PB2 2164
#define O_PW3 2180
#define O_PB3 2436
#define O_DW1 2452
#define O_DW2 2692
#define O_DB2 2948
#define O_DW3 2964
#define O_DB3 3220
#define O_DW4 3236
#define O_DB4 3284
#define SW_TOT 3288

// packed layer: IN scalar inputs -> OUT (=2*OUTH) packed accumulators
template<int IN, int OUTH>
__device__ __forceinline__ void layer2(const float* __restrict__ x,
                                       const float* __restrict__ sw_w,
                                       const float* __restrict__ sw_b,
                                       u64* acc) {
    const u64* b2 = reinterpret_cast<const u64*>(sw_b);
#pragma unroll
    for (int j = 0; j < OUTH; j++) acc[j] = b2[j];
#pragma unroll
    for (int i = 0; i < IN; i++) {
        u64 xb = pk2(x[i], x[i]);
        const ulonglong2* w = reinterpret_cast<const ulonglong2*>(sw_w + i * (2*OUTH));
#pragma unroll
        for (int j = 0; j < OUTH/2; j++) {
            ulonglong2 ww = w[j];
            fma2(acc[2*j+0], xb, ww.x);
            fma2(acc[2*j+1], xb, ww.y);
        }
    }
}

template<int OUTH>
__device__ __forceinline__ void relu_unpack(const u64* acc, float* out) {
#pragma unroll
    for (int j = 0; j < OUTH; j++) {
        float a, b; upk2(acc[j], a, b);
        out[2*j]   = fmaxf(a, 0.f);
        out[2*j+1] = fmaxf(b, 0.f);
    }
}

__global__ __launch_bounds__(256) void k_phaseA(
    const float* __restrict__ ro, const float* __restrict__ rd,
    const float* __restrict__ aw1, const float* __restrict__ ab1,
    const float* __restrict__ aw2, const float* __restrict__ ab2,
    const float* __restrict__ aw3, const float* __restrict__ ab3,
    const float* __restrict__ pw1, const float* __restrict__ pb1,
    const float* __restrict__ pw2, const float* __restrict__ pb2,
    const float* __restrict__ pw3, const float* __restrict__ pb3,
    const float* __restrict__ dw1,
    const float* __restrict__ dw2, const float* __restrict__ db2,
    const float* __restrict__ dw3, const float* __restrict__ db3,
    const float* __restrict__ dw4, const float* __restrict__ db4)
{
    __shared__ float sw[SW_TOT];
    __shared__ float s_db[16];
    __shared__ float s_ray[9];   // tmin, |d|, mask, ox,oy,oz, dx,dy,dz
    {
        int t = threadIdx.x;
        for (int i = t; i < 480;  i += 256) sw[O_AW1 + i] = aw1[i];
        for (int i = t; i < 32;   i += 256) sw[O_AB1 + i] = ab1[i];
        for (int i = t; i < 1024; i += 256) sw[O_AW2 + i] = aw2[i];
        for (int i = t; i < 32;   i += 256) sw[O_AB2 + i] = ab2[i];
        for (int i = t; i < 128;  i += 256) sw[O_AW3 + i] = aw3[i];
        for (int i = t; i < 4;    i += 256) sw[O_AB3 + i] = ab3[i];
        for (int i = t; i < 192;  i += 256) sw[O_PW1 + i] = pw1[i];
        for (int i = t; i < 16;   i += 256) sw[O_PB1 + i] = pb1[i];
        for (int i = t; i < 256;  i += 256) sw[O_PW2 + i] = pw2[i];
        for (int i = t; i < 16;   i += 256) sw[O_PB2 + i] = pb2[i];
        for (int i = t; i < 256;  i += 256) sw[O_PW3 + i] = pw3[i];
        for (int i = t; i < 16;   i += 256) sw[O_PB3 + i] = pb3[i];
        for (int i = t; i < 240;  i += 256) sw[O_DW1 + i] = dw1[i];  // rows 0..14 only
        for (int i = t; i < 256;  i += 256) sw[O_DW2 + i] = dw2[i];
        for (int i = t; i < 16;   i += 256) sw[O_DB2 + i] = db2[i];
        for (int i = t; i < 256;  i += 256) sw[O_DW3 + i] = dw3[i];
        for (int i = t; i < 16;   i += 256) sw[O_DB3 + i] = db3[i];
        for (int i = t; i < 48;   i += 256) sw[O_DW4 + i] = dw4[i];
        for (int i = t; i < 3;    i += 256) sw[O_DB4 + i] = db4[i];
        int ray0 = blockIdx.y;
        if (t < 16) s_db[t] = g_dbias[16*ray0 + t];
        if (t < 3)  s_ray[t] = g_rayinfo[4*ray0 + t];
        if (t >= 3 && t < 6) s_ray[t] = ro[3*ray0 + (t-3)];
        if (t >= 6 && t < 9) s_ray[t] = rd[3*ray0 + (t-6)];
    }
    __syncthreads();

    int ray = blockIdx.y;
    int s = blockIdx.x * 256 + threadIdx.x;
    if (s >= NS) return;
    int oi = ray * NS + s;

    float tmn = s_ray[0], rn = s_ray[1], mask = s_ray[2];
    float it = tmn + STEPW * (float)s / rn;
    float px = s_ray[3] + s_ray[6] * it;
    float py = s_ray[4] + s_ray[7] * it;
    float pz = s_ray[5] + s_ray[8] * it;
    bool inb = (mask == 0.f) &&
               px >= -1.f && px <= 1.f &&
               py >= -1.f && py <= 1.f &&
               pz >= -1.f && pz <= 1.f;
    if (!inb) { g_scratch[oi] = make_float4(0.f, 0.f, 0.f, 0.f); return; }

    // ---- trilinear from channel-last grid (packed accumulators) ----
    float gx = (px + 1.f) * 0.5f * 159.f;
    float gy = (py + 1.f) * 0.5f * 159.f;
    float gz = (pz + 1.f) * 0.5f * 159.f;
    float fx0 = floorf(gx), fy0 = floorf(gy), fz0 = floorf(gz);
    float wx1 = gx - fx0, wy1 = gy - fy0, wz1 = gz - fz0;
    float wx0 = 1.f - wx1, wy0 = 1.f - wy1, wz0 = 1.f - wz1;
    int ix0 = min(max((int)fx0, 0), 159); int ix1 = min(ix0 + 1, 159);
    int iy0 = min(max((int)fy0, 0), 159); int iy1 = min(iy0 + 1, 159);
    int iz0 = min(max((int)fz0, 0), 159); int iz1 = min(iz0 + 1, 159);

    u64 lat2[6];
#pragma unroll
    for (int k = 0; k < 6; k++) lat2[k] = 0ull;

#define ADD_CORNER(X, Y, Z, W) {                                                     \
        const ulonglong2* gp = reinterpret_cast<const ulonglong2*>(                  \
            g_grid_t + (size_t)((((X)*160 + (Y))*160) + (Z)) * 12);                  \
        ulonglong2 A = __ldg(gp), B = __ldg(gp+1), C = __ldg(gp+2);                  \
        float W_ = (W);                                                              \
        u64 wb = pk2(W_, W_);                                                        \
        fma2(lat2[0], wb, A.x); fma2(lat2[1], wb, A.y);                              \
        fma2(lat2[2], wb, B.x); fma2(lat2[3], wb, B.y);                              \
        fma2(lat2[4], wb, C.x); fma2(lat2[5], wb, C.y); }

    ADD_CORNER(ix0, iy0, iz0, wx0*wy0*wz0);
    ADD_CORNER(ix0, iy0, iz1, wx0*wy0*wz1);
    ADD_CORNER(ix0, iy1, iz0, wx0*wy1*wz0);
    ADD_CORNER(ix0, iy1, iz1, wx0*wy1*wz1);
    ADD_CORNER(ix1, iy0, iz0, wx1*wy0*wz0);
    ADD_CORNER(ix1, iy0, iz1, wx1*wy0*wz1);
    ADD_CORNER(ix1, iy1, iz0, wx1*wy1*wz0);
    ADD_CORNER(ix1, iy1, iz1, wx1*wy1*wz1);
#undef ADD_CORNER

    float lat[12];
#pragma unroll
    for (int k = 0; k < 6; k++) upk2(lat2[k], lat[2*k], lat[2*k+1]);

    // ---- attention MLP: [pz,py,px, lat] (15) -> 32 -> 32 -> 4 -> softmax[1]
    float xin[15];
    xin[0] = pz; xin[1] = py; xin[2] = px;
#pragma unroll
    for (int k = 0; k < 12; k++) xin[3+k] = lat[k];

    u64 acc16[16];
    float h1[32], h2[32];
    layer2<15, 16>(xin, &sw[O_AW1], &sw[O_AB1], acc16);
    relu_unpack<16>(acc16, h1);
    layer2<32, 16>(h1, &sw[O_AW2], &sw[O_AB2], acc16);
    relu_unpack<16>(acc16, h2);

    u64 accO[2];
    layer2<32, 2>(h2, &sw[O_AW3], &sw[O_AB3], accO);
    float o0, o1, o2, o3;
    upk2(accO[0], o0, o1); upk2(accO[1], o2, o3);
    float mx = fmaxf(fmaxf(o0, o1), fmaxf(o2, o3));
    float e0 = expf(o0-mx), e1 = expf(o1-mx), e2 = expf(o2-mx), e3 = expf(o3-mx);
    float att1 = e1 / (e0 + e1 + e2 + e3);

    // ---- pos MLP: lat (12) -> 16 -> 16 -> 16 ----
    u64 acc8[8];
    float p1[16], p2[16], p3[16];
    layer2<12, 8>(lat, &sw[O_PW1], &sw[O_PB1], acc8);
    relu_unpack<8>(acc8, p1);
    layer2<16, 8>(p1, &sw[O_PW2], &sw[O_PB2], acc8);
    relu_unpack<8>(acc8, p2);
    layer2<16, 8>(p2, &sw[O_PW3], &sw[O_PB3], acc8);
#pragma unroll
    for (int j = 0; j < 8; j++) upk2(acc8[j], p3[2*j], p3[2*j+1]);  // no relu

    // ---- dir MLP: [p3[1:16] ; emb(folded bias)] -> 16 -> 16 -> 16 -> 3 ----
    float d1[16], d2[16], d3[16];
    layer2<15, 8>(&p3[1], &sw[O_DW1], s_db, acc8);
    relu_unpack<8>(acc8, d1);
    layer2<16, 8>(d1, &sw[O_DW2], &sw[O_DB2], acc8);
    relu_unpack<8>(acc8, d2);
    layer2<16, 8>(d2, &sw[O_DW3], &sw[O_DB3], acc8);
    relu_unpack<8>(acc8, d3);

    float r0 = sw[O_DB4+0], r1 = sw[O_DB4+1], r2 = sw[O_DB4+2];
#pragma unroll
    for (int i = 0; i < 16; i++) {
        float xi = d3[i];
        r0 += xi * sw[O_DW4 + i*3 + 0];
        r1 += xi * sw[O_DW4 + i*3 + 1];
        r2 += xi * sw[O_DW4 + i*3 + 2];
    }

    // ---- activations ----
    float dens = att1 * p3[0];
    float xs = dens + ACT_SHIFT;
    float sp = fmaxf(xs, 0.f) + log1pf(expf(-fabsf(xs)));   // softplus
    float alpha = 1.f - expf(-sp * 0.5f);
    float c0 = 1.f / (1.f + expf(-att1 * r0));
    float c1 = 1.f / (1.f + expf(-att1 * r1));
    float c2 = 1.f / (1.f + expf(-att1 * r2));

    g_scratch[oi] = make_float4(alpha, c0, c1, c2);
}

// =====================================================================
// Kernel 3: warp-per-ray alpha compositing (shfl prefix-product scan)
// =====================================================================
__global__ __launch_bounds__(256) void k_phaseB(float* __restrict__ out) {
    int gid  = blockIdx.x * blockDim.x + threadIdx.x;
    int ray  = gid >> 5;
    int lane = gid & 31;
    if (ray >= NRAY) return;

    float tmn = g_rayinfo[4*ray], rn = g_rayinfo[4*ray+1];
    float base_depth = tmn * rn;

    float T = 1.f;
    float sr = 0.f, sg = 0.f, sb = 0.f, sd = 0.f, sa = 0.f;

    for (int c0 = 0; c0 < NS; c0 += 32) {
        int s = c0 + lane;
        float4 rec = make_float4(0.f, 0.f, 0.f, 0.f);
        if (s < NS) rec = g_scratch[ray*NS + s];
        float a = rec.x;
        float q = fmaxf(1.f - a, 1e-10f);
        float ip = q;
#pragma unroll
        for (int off = 1; off < 32; off <<= 1) {
            float v = __shfl_up_sync(0xFFFFFFFFu, ip, off);
            if (lane >= off) ip *= v;
        }
        float ep = __shfl_up_sync(0xFFFFFFFFu, ip, 1);
        if (lane == 0) ep = 1.f;
        float w = a * T * ep;
        sr += w * rec.y;
        sg += w * rec.z;
        sb += w * rec.w;
        sd += w * (base_depth + STEPW * (float)s);
        sa += w;
        T *= __shfl_sync(0xFFFFFFFFu, ip, 31);
    }

#pragma unroll
    for (int off = 16; off > 0; off >>= 1) {
        sr += __shfl_xor_sync(0xFFFFFFFFu, sr, off);
        sg += __shfl_xor_sync(0xFFFFFFFFu, sg, off);
        sb += __shfl_xor_sync(0xFFFFFFFFu, sb, off);
        sd += __shfl_xor_sync(0xFFFFFFFFu, sd, off);
        sa += __shfl_xor_sync(0xFFFFFFFFu, sa, off);
    }

    if (lane == 0) {
        float depth = sd + T * FARC;
        out[ray*6+0] = sr + T * BGC;
        out[ray*6+1] = sg + T * BGC;
        out[ray*6+2] = sb + T * BGC;
        out[ray*6+3] = depth;
        out[ray*6+4] = 1.f / depth;
        out[ray*6+5] = sa;
    }
}

// =====================================================================
extern "C" void kernel_launch(void* const* d_in, const int* in_sizes, int n_in,
                              void* d_out, int out_size) {
    const float* ro  = (const float*)d_in[0];
    const float* rd  = (const float*)d_in[1];
    const float* vd  = (const float*)d_in[2];
    const float* grd = (const float*)d_in[3];
    const float* aw1 = (const float*)d_in[4];
    const float* ab1 = (const float*)d_in[5];
    const float* aw2 = (const float*)d_in[6];
    const float* ab2 = (const float*)d_in[7];
    const float* aw3 = (const float*)d_in[8];
    const float* ab3 = (const float*)d_in[9];
    const float* pw1 = (const float*)d_in[10];
    const float* pb1 = (const float*)d_in[11];
    const float* pw2 = (const float*)d_in[12];
    const float* pb2 = (const float*)d_in[13];
    const float* pw3 = (const float*)d_in[14];
    const float* pb3 = (const float*)d_in[15];
    const float* dw1 = (const float*)d_in[16];
    const float* db1 = (const float*)d_in[17];
    const float* dw2 = (const float*)d_in[18];
    const float* db2 = (const float*)d_in[19];
    const float* dw3 = (const float*)d_in[20];
    const float* db3 = (const float*)d_in[21];
    const float* dw4 = (const float*)d_in[22];
    const float* db4 = (const float*)d_in[23];

    k_transpose<<<R3 / 256, 256>>>(grd);
    k_raypre<<<(NRAY + 255) / 256, 256>>>(ro, rd, vd, dw1, db1);
    dim3 gA((NS + 255) / 256, NRAY);
    k_phaseA<<<gA, 256>>>(ro, rd,
                          aw1, ab1, aw2, ab2, aw3, ab3,
                          pw1, pb1, pw2, pb2, pw3, pb3,
                          dw1, dw2, db2, dw3, db3, dw4, db4);
    k_phaseB<<<(NRAY * 32) / 256, 256>>>((float*)d_out);
}

// round 15
// speedup vs baseline: 1.7189x; 1.0887x over previous
#include <cuda_runtime.h>
#include <cuda_fp16.h>
#include <math.h>

#define RES   160
#define R3    (RES*RES*RES)
#define NRAY  2048
#define NS    558
#define NEARC 0.05f
#define FARC  3.5f
#define BGC   1.0f
#define STEPW 0.00625f                 /* STEPSIZE * VOXEL = 0.5 * 0.0125 */
#define ACT_SHIFT -4.5951198501345898f /* log(1/(1-0.01)-1) */

typedef unsigned long long u64;
typedef unsigned int u32;

// ---- packed f32x2 helpers (Blackwell-only; ptxas never auto-fuses FFMA2) ----
__device__ __forceinline__ u64 pk2(float lo, float hi) {
    u64 r; asm("mov.b64 %0, {%1, %2};" : "=l"(r) : "f"(lo), "f"(hi)); return r;
}
__device__ __forceinline__ void upk2(u64 v, float& lo, float& hi) {
    asm("mov.b64 {%0, %1}, %2;" : "=f"(lo), "=f"(hi) : "l"(v));
}
__device__ __forceinline__ void fma2(u64& d, u64 a, u64 b) {
    asm("fma.rn.f32x2 %0, %1, %2, %0;" : "+l"(d) : "l"(a), "l"(b));
}
// unpack u64 of 4 halfs -> two packed f32x2 values
__device__ __forceinline__ void h4_to_f2x2(u64 h4, u64& lo2, u64& hi2) {
    u32 l = (u32)h4, h = (u32)(h4 >> 32);
    __half2 hl = *reinterpret_cast<__half2*>(&l);
    __half2 hh = *reinterpret_cast<__half2*>(&h);
    float2 fl = __half22float2(hl);
    float2 fh = __half22float2(hh);
    lo2 = pk2(fl.x, fl.y);
    hi2 = pk2(fh.x, fh.y);
}

// ---- device scratch (static; no allocations allowed) ----
__device__ __half g_grid_h[(size_t)R3 * 12];   // channel-last fp16 grid, 98.3 MB
__device__ float4 g_scratch[NRAY * NS];        // {alpha, r, g, b} per sample
__device__ float  g_rayinfo[NRAY * 4];         // tmin, |d|, mask, pad
__device__ float  g_dbias[NRAY * 16];          // per-ray dir-layer1 bias (emb folded)

// =====================================================================
// Kernel 0: transpose grid (C,R,R,R) fp32 -> (R,R,R,C) fp16
// smem-staged: coalesced LDG (lane-stride 4B) AND coalesced u32 stores
// =====================================================================
__global__ __launch_bounds__(256) void k_transpose(const float* __restrict__ g) {
    __shared__ __align__(16) __half tile[256 * 12];   // 6 KB
    int v0 = blockIdx.x * 256;
    int t  = threadIdx.x;
    int v  = v0 + t;                                  // R3 % 256 == 0
#pragma unroll
    for (int c = 0; c < 12; c++)
        tile[t * 12 + c] = __float2half_rn(__ldg(g + (size_t)c * R3 + v));
    __syncthreads();
    u32* dst = reinterpret_cast<u32*>(g_grid_h + (size_t)v0 * 12);
    const u32* src = reinterpret_cast<const u32*>(tile);
#pragma unroll
    for (int i = 0; i < 6; i++)                       // 1536 u32 words
        dst[i * 256 + t] = src[i * 256 + t];
}

// =====================================================================
// Kernel 1: per-ray precompute (tmin, |d|, mask, dir-layer1 bias)
// =====================================================================
__global__ void k_raypre(const float* __restrict__ ro, const float* __restrict__ rd,
                         const float* __restrict__ vd, const float* __restrict__ dw1,
                         const float* __restrict__ db1) {
    int r = blockIdx.x * blockDim.x + threadIdx.x;
    if (r >= NRAY) return;
    float ox = ro[3*r], oy = ro[3*r+1], oz = ro[3*r+2];
    float dx = rd[3*r], dy = rd[3*r+1], dz = rd[3*r+2];
    float vx = (dx == 0.f) ? 1e-6f : dx;
    float vy = (dy == 0.f) ? 1e-6f : dy;
    float vz = (dz == 0.f) ? 1e-6f : dz;
    float rax = (1.f - ox) / vx, rbx = (-1.f - ox) / vx;
    float ray_ = (1.f - oy) / vy, rby = (-1.f - oy) / vy;
    float raz = (1.f - oz) / vz, rbz = (-1.f - oz) / vz;
    float tmn = fmaxf(fmaxf(fminf(rax, rbx), fminf(ray_, rby)), fminf(raz, rbz));
    float tmx = fminf(fminf(fmaxf(rax, rbx), fmaxf(ray_, rby)), fmaxf(raz, rbz));
    tmn = fminf(fmaxf(tmn, NEARC), FARC);
    tmx = fminf(fmaxf(tmx, NEARC), FARC);
    float mask = (tmx <= tmn) ? 1.f : 0.f;
    float nn = sqrtf(dx*dx + dy*dy + dz*dz);
    g_rayinfo[4*r+0] = tmn;
    g_rayinfo[4*r+1] = nn;
    g_rayinfo[4*r+2] = mask;
    g_rayinfo[4*r+3] = 0.f;

    // positional encoding of viewdir (per-ray constant) folded into dir bias
    float wx = vd[3*r], wy = vd[3*r+1], wz = vd[3*r+2];
    float emb[39];
    emb[0] = wx; emb[1] = wy; emb[2] = wz;
    float f = 1.f;
#pragma unroll
    for (int l = 0; l < 6; l++) {
        emb[3+6*l+0] = sinf(wx*f); emb[3+6*l+1] = sinf(wy*f); emb[3+6*l+2] = sinf(wz*f);
        emb[3+6*l+3] = cosf(wx*f); emb[3+6*l+4] = cosf(wy*f); emb[3+6*l+5] = cosf(wz*f);
        f *= 2.f;
    }
#pragma unroll
    for (int j = 0; j < 16; j++) {
        float acc = db1[j];
#pragma unroll
        for (int k = 0; k < 39; k++) acc += emb[k] * dw1[(15+k)*16 + j];
        g_dbias[16*r + j] = acc;
    }
}

// =====================================================================
// Kernel 2: per-sample MLP evaluation -> scratch {alpha, rgb}
// grid: (ceil(NS/256), NRAY); MLP code identical to 200.8us build
// =====================================================================
#define O_AW1 0
#define O_AB1 480
#define O_AW2 512
#define O_AB2 1536
#define O_AW3 1568
#define O_AB3 1696
#define O_PW1 1700
#define O_PB1 1892
#define O_PW2 1908
#define O_PB2 2164
#define O_PW3 2180
#define O_PB3 2436
#define O_DW1 2452
#define O_DW2 2692
#define O_DB2 2948
#define O_DW3 2964
#define O_DB3 3220
#define O_DW4 3236
#define O_DB4 3284
#define SW_TOT 3288

// packed layer: IN scalar inputs -> OUT (=2*OUTH) packed accumulators
template<int IN, int OUTH>
__device__ __forceinline__ void layer2(const float* __restrict__ x,
                                       const float* __restrict__ sw_w,
                                       const float* __restrict__ sw_b,
                                       u64* acc) {
    const u64* b2 = reinterpret_cast<const u64*>(sw_b);
#pragma unroll
    for (int j = 0; j < OUTH; j++) acc[j] = b2[j];
#pragma unroll
    for (int i = 0; i < IN; i++) {
        u64 xb = pk2(x[i], x[i]);
        const ulonglong2* w = reinterpret_cast<const ulonglong2*>(sw_w + i * (2*OUTH));
#pragma unroll
        for (int j = 0; j < OUTH/2; j++) {
            ulonglong2 ww = w[j];
            fma2(acc[2*j+0], xb, ww.x);
            fma2(acc[2*j+1], xb, ww.y);
        }
    }
}

template<int OUTH>
__device__ __forceinline__ void relu_unpack(const u64* acc, float* out) {
#pragma unroll
    for (int j = 0; j < OUTH; j++) {
        float a, b; upk2(acc[j], a, b);
        out[2*j]   = fmaxf(a, 0.f);
        out[2*j+1] = fmaxf(b, 0.f);
    }
}

__global__ __launch_bounds__(256) void k_phaseA(
    const float* __restrict__ ro, const float* __restrict__ rd,
    const float* __restrict__ aw1, const float* __restrict__ ab1,
    const float* __restrict__ aw2, const float* __restrict__ ab2,
    const float* __restrict__ aw3, const float* __restrict__ ab3,
    const float* __restrict__ pw1, const float* __restrict__ pb1,
    const float* __restrict__ pw2, const float* __restrict__ pb2,
    const float* __restrict__ pw3, const float* __restrict__ pb3,
    const float* __restrict__ dw1,
    const float* __restrict__ dw2, const float* __restrict__ db2,
    const float* __restrict__ dw3, const float* __restrict__ db3,
    const float* __restrict__ dw4, const float* __restrict__ db4)
{
    __shared__ float sw[SW_TOT];
    __shared__ float s_db[16];
    __shared__ float s_ray[9];   // tmin, |d|, mask, ox,oy,oz, dx,dy,dz
    {
        int t = threadIdx.x;
        for (int i = t; i < 480;  i += 256) sw[O_AW1 + i] = aw1[i];
        for (int i = t; i < 32;   i += 256) sw[O_AB1 + i] = ab1[i];
        for (int i = t; i < 1024; i += 256) sw[O_AW2 + i] = aw2[i];
        for (int i = t; i < 32;   i += 256) sw[O_AB2 + i] = ab2[i];
        for (int i = t; i < 128;  i += 256) sw[O_AW3 + i] = aw3[i];
        for (int i = t; i < 4;    i += 256) sw[O_AB3 + i] = ab3[i];
        for (int i = t; i < 192;  i += 256) sw[O_PW1 + i] = pw1[i];
        for (int i = t; i < 16;   i += 256) sw[O_PB1 + i] = pb1[i];
        for (int i = t; i < 256;  i += 256) sw[O_PW2 + i] = pw2[i];
        for (int i = t; i < 16;   i += 256) sw[O_PB2 + i] = pb2[i];
        for (int i = t; i < 256;  i += 256) sw[O_PW3 + i] = pw3[i];
        for (int i = t; i < 16;   i += 256) sw[O_PB3 + i] = pb3[i];
        for (int i = t; i < 240;  i += 256) sw[O_DW1 + i] = dw1[i];  // rows 0..14 only
        for (int i = t; i < 256;  i += 256) sw[O_DW2 + i] = dw2[i];
        for (int i = t; i < 16;   i += 256) sw[O_DB2 + i] = db2[i];
        for (int i = t; i < 256;  i += 256) sw[O_DW3 + i] = dw3[i];
        for (int i = t; i < 16;   i += 256) sw[O_DB3 + i] = db3[i];
        for (int i = t; i < 48;   i += 256) sw[O_DW4 + i] = dw4[i];
        for (int i = t; i < 3;    i += 256) sw[O_DB4 + i] = db4[i];
        int ray0 = blockIdx.y;
        if (t < 16) s_db[t] = g_dbias[16*ray0 + t];
        if (t < 3)  s_ray[t] = g_rayinfo[4*ray0 + t];
        if (t >= 3 && t < 6) s_ray[t] = ro[3*ray0 + (t-3)];
        if (t >= 6 && t < 9) s_ray[t] = rd[3*ray0 + (t-6)];
    }
    __syncthreads();

    int ray = blockIdx.y;
    int s = blockIdx.x * 256 + threadIdx.x;
    if (s >= NS) return;
    int oi = ray * NS + s;

    float tmn = s_ray[0], rn = s_ray[1], mask = s_ray[2];
    float it = tmn + STEPW * (float)s / rn;
    float px = s_ray[3] + s_ray[6] * it;
    float py = s_ray[4] + s_ray[7] * it;
    float pz = s_ray[5] + s_ray[8] * it;
    bool inb = (mask == 0.f) &&
               px >= -1.f && px <= 1.f &&
               py >= -1.f && py <= 1.f &&
               pz >= -1.f && pz <= 1.f;
    if (!inb) { g_scratch[oi] = make_float4(0.f, 0.f, 0.f, 0.f); return; }

    // ---- trilinear from channel-last fp16 grid (fp32 accumulation) ----
    float gx = (px + 1.f) * 0.5f * 159.f;
    float gy = (py + 1.f) * 0.5f * 159.f;
    float gz = (pz + 1.f) * 0.5f * 159.f;
    float fx0 = floorf(gx), fy0 = floorf(gy), fz0 = floorf(gz);
    float wx1 = gx - fx0, wy1 = gy - fy0, wz1 = gz - fz0;
    float wx0 = 1.f - wx1, wy0 = 1.f - wy1, wz0 = 1.f - wz1;
    int ix0 = min(max((int)fx0, 0), 159); int ix1 = min(ix0 + 1, 159);
    int iy0 = min(max((int)fy0, 0), 159); int iy1 = min(iy0 + 1, 159);
    int iz0 = min(max((int)fz0, 0), 159); int iz1 = min(iz0 + 1, 159);

    u64 lat2[6];
#pragma unroll
    for (int k = 0; k < 6; k++) lat2[k] = 0ull;

#define ADD_CORNER(X, Y, Z, W) {                                                     \
        const u64* gp = reinterpret_cast<const u64*>(                                \
            g_grid_h + (size_t)((((X)*160 + (Y))*160) + (Z)) * 12);                  \
        u64 A = __ldg(gp), B = __ldg(gp+1), C = __ldg(gp+2);                         \
        float W_ = (W);                                                              \
        u64 wb = pk2(W_, W_);                                                        \
        u64 f0, f1;                                                                  \
        h4_to_f2x2(A, f0, f1); fma2(lat2[0], wb, f0); fma2(lat2[1], wb, f1);         \
        h4_to_f2x2(B, f0, f1); fma2(lat2[2], wb, f0); fma2(lat2[3], wb, f1);         \
        h4_to_f2x2(C, f0, f1); fma2(lat2[4], wb, f0); fma2(lat2[5], wb, f1); }

    ADD_CORNER(ix0, iy0, iz0, wx0*wy0*wz0);
    ADD_CORNER(ix0, iy0, iz1, wx0*wy0*wz1);
    ADD_CORNER(ix0, iy1, iz0, wx0*wy1*wz0);
    ADD_CORNER(ix0, iy1, iz1, wx0*wy1*wz1);
    ADD_CORNER(ix1, iy0, iz0, wx1*wy0*wz0);
    ADD_CORNER(ix1, iy0, iz1, wx1*wy0*wz1);
    ADD_CORNER(ix1, iy1, iz0, wx1*wy1*wz0);
    ADD_CORNER(ix1, iy1, iz1, wx1*wy1*wz1);
#undef ADD_CORNER

    float lat[12];
#pragma unroll
    for (int k = 0; k < 6; k++) upk2(lat2[k], lat[2*k], lat[2*k+1]);

    // ---- attention MLP: [pz,py,px, lat] (15) -> 32 -> 32 -> 4 -> softmax[1]
    float xin[15];
    xin[0] = pz; xin[1] = py; xin[2] = px;
#pragma unroll
    for (int k = 0; k < 12; k++) xin[3+k] = lat[k];

    u64 acc16[16];
    float h1[32], h2[32];
    layer2<15, 16>(xin, &sw[O_AW1], &sw[O_AB1], acc16);
    relu_unpack<16>(acc16, h1);
    layer2<32, 16>(h1, &sw[O_AW2], &sw[O_AB2], acc16);
    relu_unpack<16>(acc16, h2);

    u64 accO[2];
    layer2<32, 2>(h2, &sw[O_AW3], &sw[O_AB3], accO);
    float o0, o1, o2, o3;
    upk2(accO[0], o0, o1); upk2(accO[1], o2, o3);
    float mx = fmaxf(fmaxf(o0, o1), fmaxf(o2, o3));
    float e0 = expf(o0-mx), e1 = expf(o1-mx), e2 = expf(o2-mx), e3 = expf(o3-mx);
    float att1 = e1 / (e0 + e1 + e2 + e3);

    // ---- pos MLP: lat (12) -> 16 -> 16 -> 16 ----
    u64 acc8[8];
    float p1[16], p2[16], p3[16];
    layer2<12, 8>(lat, &sw[O_PW1], &sw[O_PB1], acc8);
    relu_unpack<8>(acc8, p1);
    layer2<16, 8>(p1, &sw[O_PW2], &sw[O_PB2], acc8);
    relu_unpack<8>(acc8, p2);
    layer2<16, 8>(p2, &sw[O_PW3], &sw[O_PB3], acc8);
#pragma unroll
    for (int j = 0; j < 8; j++) upk2(acc8[j], p3[2*j], p3[2*j+1]);  // no relu

    // ---- dir MLP: [p3[1:16] ; emb(folded bias)] -> 16 -> 16 -> 16 -> 3 ----
    float d1[16], d2[16], d3[16];
    layer2<15, 8>(&p3[1], &sw[O_DW1], s_db, acc8);
    relu_unpack<8>(acc8, d1);
    layer2<16, 8>(d1, &sw[O_DW2], &sw[O_DB2], acc8);
    relu_unpack<8>(acc8, d2);
    layer2<16, 8>(d2, &sw[O_DW3], &sw[O_DB3], acc8);
    relu_unpack<8>(acc8, d3);

    float r0 = sw[O_DB4+0], r1 = sw[O_DB4+1], r2 = sw[O_DB4+2];
#pragma unroll
    for (int i = 0; i < 16; i++) {
        float xi = d3[i];
        r0 += xi * sw[O_DW4 + i*3 + 0];
        r1 += xi * sw[O_DW4 + i*3 + 1];
        r2 += xi * sw[O_DW4 + i*3 + 2];
    }

    // ---- activations ----
    float dens = att1 * p3[0];
    float xs = dens + ACT_SHIFT;
    float sp = fmaxf(xs, 0.f) + log1pf(expf(-fabsf(xs)));   // softplus
    float alpha = 1.f - expf(-sp * 0.5f);
    float c0 = 1.f / (1.f + expf(-att1 * r0));
    float c1 = 1.f / (1.f + expf(-att1 * r1));
    float c2 = 1.f / (1.f + expf(-att1 * r2));

    g_scratch[oi] = make_float4(alpha, c0, c1, c2);
}

// =====================================================================
// Kernel 3: warp-per-ray alpha compositing (shfl prefix-product scan)
// =====================================================================
__global__ __launch_bounds__(256) void k_phaseB(float* __restrict__ out) {
    int gid  = blockIdx.x * blockDim.x + threadIdx.x;
    int ray  = gid >> 5;
    int lane = gid & 31;
    if (ray >= NRAY) return;

    float tmn = g_rayinfo[4*ray], rn = g_rayinfo[4*ray+1];
    float base_depth = tmn * rn;

    float T = 1.f;
    float sr = 0.f, sg = 0.f, sb = 0.f, sd = 0.f, sa = 0.f;

    for (int c0 = 0; c0 < NS; c0 += 32) {
        int s = c0 + lane;
        float4 rec = make_float4(0.f, 0.f, 0.f, 0.f);
        if (s < NS) rec = g_scratch[ray*NS + s];
        float a = rec.x;
        float q = fmaxf(1.f - a, 1e-10f);
        float ip = q;
#pragma unroll
        for (int off = 1; off < 32; off <<= 1) {
            float v = __shfl_up_sync(0xFFFFFFFFu, ip, off);
            if (lane >= off) ip *= v;
        }
        float ep = __shfl_up_sync(0xFFFFFFFFu, ip, 1);
        if (lane == 0) ep = 1.f;
        float w = a * T * ep;
        sr += w * rec.y;
        sg += w * rec.z;
        sb += w * rec.w;
        sd += w * (base_depth + STEPW * (float)s);
        sa += w;
        T *= __shfl_sync(0xFFFFFFFFu, ip, 31);
    }

#pragma unroll
    for (int off = 16; off > 0; off >>= 1) {
        sr += __shfl_xor_sync(0xFFFFFFFFu, sr, off);
        sg += __shfl_xor_sync(0xFFFFFFFFu, sg, off);
        sb += __shfl_xor_sync(0xFFFFFFFFu, sb, off);
        sd += __shfl_xor_sync(0xFFFFFFFFu, sd, off);
        sa += __shfl_xor_sync(0xFFFFFFFFu, sa, off);
    }

    if (lane == 0) {
        float depth = sd + T * FARC;
        out[ray*6+0] = sr + T * BGC;
        out[ray*6+1] = sg + T * BGC;
        out[ray*6+2] = sb + T * BGC;
        out[ray*6+3] = depth;
        out[ray*6+4] = 1.f / depth;
        out[ray*6+5] = sa;
    }
}

// =====================================================================
extern "C" void kernel_launch(void* const* d_in, const int* in_sizes, int n_in,
                              void* d_out, int out_size) {
    const float* ro  = (const float*)d_in[0];
    const float* rd  = (const float*)d_in[1];
    const float* vd  = (const float*)d_in[2];
    const float* grd = (const float*)d_in[3];
    const float* aw1 = (const float*)d_in[4];
    const float* ab1 = (const float*)d_in[5];
    const float* aw2 = (const float*)d_in[6];
    const float* ab2 = (const float*)d_in[7];
    const float* aw3 = (const float*)d_in[8];
    const float* ab3 = (const float*)d_in[9];
    const float* pw1 = (const float*)d_in[10];
    const float* pb1 = (const float*)d_in[11];
    const float* pw2 = (const float*)d_in[12];
    const float* pb2 = (const float*)d_in[13];
    const float* pw3 = (const float*)d_in[14];
    const float* pb3 = (const float*)d_in[15];
    const float* dw1 = (const float*)d_in[16];
    const float* db1 = (const float*)d_in[17];
    const float* dw2 = (const float*)d_in[18];
    const float* db2 = (const float*)d_in[19];
    const float* dw3 = (const float*)d_in[20];
    const float* db3 = (const float*)d_in[21];
    const float* dw4 = (const float*)d_in[22];
    const float* db4 = (const float*)d_in[23];

    k_transpose<<<R3 / 256, 256>>>(grd);
    k_raypre<<<(NRAY + 255) / 256, 256>>>(ro, rd, vd, dw1, db1);
    dim3 gA((NS + 255) / 256, NRAY);
    k_phaseA<<<gA, 256>>>(ro, rd,
                          aw1, ab1, aw2, ab2, aw3, ab3,
                          pw1, pb1, pw2, pb2, pw3, pb3,
                          dw1, dw2, db2, dw3, db3, dw4, db4);
    k_phaseB<<<(NRAY * 32) / 256, 256>>>((float*)d_out);
}

// round 16
// speedup vs baseline: 2.2851x; 1.3294x over previous
#include <cuda_runtime.h>
#include <cuda_fp16.h>
#include <math.h>

#define RES   160
#define R3    (RES*RES*RES)
#define NRAY  2048
#define NS    558
#define NEARC 0.05f
#define FARC  3.5f
#define BGC   1.0f
#define STEPW 0.00625f                 /* STEPSIZE * VOXEL = 0.5 * 0.0125 */
#define ACT_SHIFT -4.5951198501345898f /* log(1/(1-0.01)-1) */

typedef unsigned long long u64;
typedef unsigned int u32;

// ---- packed f32x2 helpers (trilerp) ----
__device__ __forceinline__ u64 pk2(float lo, float hi) {
    u64 r; asm("mov.b64 %0, {%1, %2};" : "=l"(r) : "f"(lo), "f"(hi)); return r;
}
__device__ __forceinline__ void upk2(u64 v, float& lo, float& hi) {
    asm("mov.b64 {%0, %1}, %2;" : "=f"(lo), "=f"(hi) : "l"(v));
}
__device__ __forceinline__ void fma2(u64& d, u64 a, u64 b) {
    asm("fma.rn.f32x2 %0, %1, %2, %0;" : "+l"(d) : "l"(a), "l"(b));
}
__device__ __forceinline__ void h4_to_f2x2(u64 h4, u64& lo2, u64& hi2) {
    u32 l = (u32)h4, h = (u32)(h4 >> 32);
    __half2 hl = *reinterpret_cast<__half2*>(&l);
    __half2 hh = *reinterpret_cast<__half2*>(&h);
    float2 fl = __half22float2(hl);
    float2 fh = __half22float2(hh);
    lo2 = pk2(fl.x, fl.y);
    hi2 = pk2(fh.x, fh.y);
}

// ---- mma helpers ----
__device__ __forceinline__ void mma16816(float c[4], const u32 a[4], u32 b0, u32 b1) {
    asm volatile(
        "mma.sync.aligned.m16n8k16.row.col.f32.f16.f16.f32 "
        "{%0,%1,%2,%3}, {%4,%5,%6,%7}, {%8,%9}, {%0,%1,%2,%3};"
        : "+f"(c[0]), "+f"(c[1]), "+f"(c[2]), "+f"(c[3])
        : "r"(a[0]), "r"(a[1]), "r"(a[2]), "r"(a[3]), "r"(b0), "r"(b1));
}
// pack {lo, hi} floats into one f16x2 (lo in low half)
__device__ __forceinline__ u32 cvt2h(float lo, float hi) {
    u32 r; asm("cvt.rn.f16x2.f32 %0, %1, %2;" : "=r"(r) : "f"(hi), "f"(lo)); return r;
}

// ---- device scratch ----
__device__ __half g_grid_h[(size_t)R3 * 12];
__device__ float4 g_scratch[NRAY * NS];
__device__ float  g_rayinfo[NRAY * 4];
__device__ float  g_dbias[NRAY * 16];

// =====================================================================
// Kernel 0: transpose grid fp32 (C,R,R,R) -> fp16 (R,R,R,C)
// =====================================================================
__global__ __launch_bounds__(256) void k_transpose(const float* __restrict__ g) {
    __shared__ __align__(16) __half tile[256 * 12];
    int v0 = blockIdx.x * 256;
    int t  = threadIdx.x;
    int v  = v0 + t;
#pragma unroll
    for (int c = 0; c < 12; c++)
        tile[t * 12 + c] = __float2half_rn(__ldg(g + (size_t)c * R3 + v));
    __syncthreads();
    u32* dst = reinterpret_cast<u32*>(g_grid_h + (size_t)v0 * 12);
    const u32* src = reinterpret_cast<const u32*>(tile);
#pragma unroll
    for (int i = 0; i < 6; i++)
        dst[i * 256 + t] = src[i * 256 + t];
}

// =====================================================================
// Kernel 1: per-ray precompute
// =====================================================================
__global__ void k_raypre(const float* __restrict__ ro, const float* __restrict__ rd,
                         const float* __restrict__ vd, const float* __restrict__ dw1,
                         const float* __restrict__ db1) {
    int r = blockIdx.x * blockDim.x + threadIdx.x;
    if (r >= NRAY) return;
    float ox = ro[3*r], oy = ro[3*r+1], oz = ro[3*r+2];
    float dx = rd[3*r], dy = rd[3*r+1], dz = rd[3*r+2];
    float vx = (dx == 0.f) ? 1e-6f : dx;
    float vy = (dy == 0.f) ? 1e-6f : dy;
    float vz = (dz == 0.f) ? 1e-6f : dz;
    float rax = (1.f - ox) / vx, rbx = (-1.f - ox) / vx;
    float ray_ = (1.f - oy) / vy, rby = (-1.f - oy) / vy;
    float raz = (1.f - oz) / vz, rbz = (-1.f - oz) / vz;
    float tmn = fmaxf(fmaxf(fminf(rax, rbx), fminf(ray_, rby)), fminf(raz, rbz));
    float tmx = fminf(fminf(fmaxf(rax, rbx), fmaxf(ray_, rby)), fmaxf(raz, rbz));
    tmn = fminf(fmaxf(tmn, NEARC), FARC);
    tmx = fminf(fmaxf(tmx, NEARC), FARC);
    float mask = (tmx <= tmn) ? 1.f : 0.f;
    float nn = sqrtf(dx*dx + dy*dy + dz*dz);
    g_rayinfo[4*r+0] = tmn;
    g_rayinfo[4*r+1] = nn;
    g_rayinfo[4*r+2] = mask;
    g_rayinfo[4*r+3] = 0.f;

    float wx = vd[3*r], wy = vd[3*r+1], wz = vd[3*r+2];
    float emb[39];
    emb[0] = wx; emb[1] = wy; emb[2] = wz;
    float f = 1.f;
#pragma unroll
    for (int l = 0; l < 6; l++) {
        emb[3+6*l+0] = sinf(wx*f); emb[3+6*l+1] = sinf(wy*f); emb[3+6*l+2] = sinf(wz*f);
        emb[3+6*l+3] = cosf(wx*f); emb[3+6*l+4] = cosf(wy*f); emb[3+6*l+5] = cosf(wz*f);
        f *= 2.f;
    }
#pragma unroll
    for (int j = 0; j < 16; j++) {
        float acc = db1[j];
#pragma unroll
        for (int k = 0; k < 39; k++) acc += emb[k] * dw1[(15+k)*16 + j];
        g_dbias[16*r + j] = acc;
    }
}

// =====================================================================
// Kernel 2: per-sample MLPs via warp-level fp16 MMA (32 samples/warp)
// grid (3, NRAY) x 256 threads. Layers as m16n8k16 GEMMs; layer chaining
// uses C(m16n8)->A(m16k16) fragment-layout identity (no shuffles).
// =====================================================================

// layer: C[NT] (each 4 f32) = A[KT] x B(tiles) + bias
template<int KT, int NT>
__device__ __forceinline__ void mlayer(const u32 A[][4], float C[][4],
                                       const u32* sB, int tileBase,
                                       const float* bias, int lane) {
    int t4 = lane & 3;
#pragma unroll
    for (int nt = 0; nt < NT; nt++) {
        float b0 = bias[nt*8 + 2*t4];
        float b1 = bias[nt*8 + 2*t4 + 1];
        C[nt][0] = b0; C[nt][1] = b1; C[nt][2] = b0; C[nt][3] = b1;
#pragma unroll
        for (int kt = 0; kt < KT; kt++) {
            int ti = tileBase + kt*NT + nt;
            mma16816(C[nt], A[kt], sB[ti*64 + lane*2], sB[ti*64 + lane*2 + 1]);
        }
    }
}

template<int NF>
__device__ __forceinline__ void relu_pack(const float C[][4], u32 A[][4]) {
#pragma unroll
    for (int f = 0; f < NF; f++) {
        A[f][0] = cvt2h(fmaxf(C[2*f][0], 0.f),   fmaxf(C[2*f][1], 0.f));
        A[f][1] = cvt2h(fmaxf(C[2*f][2], 0.f),   fmaxf(C[2*f][3], 0.f));
        A[f][2] = cvt2h(fmaxf(C[2*f+1][0], 0.f), fmaxf(C[2*f+1][1], 0.f));
        A[f][3] = cvt2h(fmaxf(C[2*f+1][2], 0.f), fmaxf(C[2*f+1][3], 0.f));
    }
}
template<int NF>
__device__ __forceinline__ void pack_norelu(const float C[][4], u32 A[][4]) {
#pragma unroll
    for (int f = 0; f < NF; f++) {
        A[f][0] = cvt2h(C[2*f][0],   C[2*f][1]);
        A[f][1] = cvt2h(C[2*f][2],   C[2*f][3]);
        A[f][2] = cvt2h(C[2*f+1][0], C[2*f+1][1]);
        A[f][3] = cvt2h(C[2*f+1][2], C[2*f+1][3]);
    }
}

__device__ __forceinline__ float4 shade(float att, float dens, float r0, float r1,
                                        float r2, float inb) {
    if (inb == 0.f) return make_float4(0.f, 0.f, 0.f, 0.f);
    float d = att * dens;
    float xs = d + ACT_SHIFT;
    float sp = fmaxf(xs, 0.f) + log1pf(expf(-fabsf(xs)));
    float alpha = 1.f - expf(-sp * 0.5f);
    float c0 = 1.f / (1.f + expf(-att * r0));
    float c1 = 1.f / (1.f + expf(-att * r1));
    float c2 = 1.f / (1.f + expf(-att * r2));
    return make_float4(alpha, c0, c1, c2);
}

__global__ __launch_bounds__(256) void k_phaseA(
    const float* __restrict__ ro, const float* __restrict__ rd,
    const float* __restrict__ aw1, const float* __restrict__ ab1,
    const float* __restrict__ aw2, const float* __restrict__ ab2,
    const float* __restrict__ aw3, const float* __restrict__ ab3,
    const float* __restrict__ pw1, const float* __restrict__ pb1,
    const float* __restrict__ pw2, const float* __restrict__ pb2,
    const float* __restrict__ pw3, const float* __restrict__ pb3,
    const float* __restrict__ dw1,
    const float* __restrict__ dw2, const float* __restrict__ db2,
    const float* __restrict__ dw3, const float* __restrict__ db3,
    const float* __restrict__ dw4, const float* __restrict__ db4)
{
    __shared__ u32  sB[27 * 64];        // B fragments (f16x2 pairs), 6912 B
    __shared__ u32  sXu[8][32][8];      // per-warp staged xin (16 halfs/sample)
    __shared__ float sBias[176];
    __shared__ float s_ray[9];

    int tid = threadIdx.x;
    int ray = blockIdx.y;

    // ---- stage B fragments (27 tiles x 64 u32) ----
    for (int e = tid; e < 27*64; e += 256) {
        int tile = e >> 6, li = (e >> 1) & 31, reg = e & 1;
        int t4 = li & 3, gq = li >> 2;
        const float* W; int stride, Oreal, klo, khi, ksh, kbase, nbase;
        if (tile < 4)       { W=aw1; stride=32; Oreal=32; klo=0; khi=15; ksh=0; kbase=0;            nbase=tile*8; }
        else if (tile < 12) { int t=tile-4;  W=aw2; stride=32; Oreal=32; klo=0; khi=32; ksh=0; kbase=(t>>2)*16; nbase=(t&3)*8; }
        else if (tile < 14) { int t=tile-12; W=aw3; stride=4;  Oreal=4;  klo=0; khi=32; ksh=0; kbase=t*16;      nbase=0; }
        else if (tile < 16) { int t=tile-14; W=pw1; stride=16; Oreal=16; klo=3; khi=15; ksh=3; kbase=0;         nbase=t*8; }
        else if (tile < 18) { int t=tile-16; W=pw2; stride=16; Oreal=16; klo=0; khi=16; ksh=0; kbase=0;         nbase=t*8; }
        else if (tile < 20) { int t=tile-18; W=pw3; stride=16; Oreal=16; klo=0; khi=16; ksh=0; kbase=0;         nbase=t*8; }
        else if (tile < 22) { int t=tile-20; W=dw1; stride=16; Oreal=16; klo=1; khi=16; ksh=1; kbase=0;         nbase=t*8; }
        else if (tile < 24) { int t=tile-22; W=dw2; stride=16; Oreal=16; klo=0; khi=16; ksh=0; kbase=0;         nbase=t*8; }
        else if (tile < 26) { int t=tile-24; W=dw3; stride=16; Oreal=16; klo=0; khi=16; ksh=0; kbase=0;         nbase=t*8; }
        else                {               W=dw4; stride=3;  Oreal=3;  klo=0; khi=16; ksh=0; kbase=0;         nbase=0; }
        int k0 = kbase + t4*2 + reg*8;
        int n  = nbase + gq;
        float v0 = 0.f, v1 = 0.f;
        if (n < Oreal) {
            int ka = k0, kb = k0 + 1;
            if (ka >= klo && ka < khi) v0 = W[(ka-ksh)*stride + n];
            if (kb >= klo && kb < khi) v1 = W[(kb-ksh)*stride + n];
        }
        sB[e] = cvt2h(v0, v1);
    }
    // ---- stage biases (padded with zeros) ----
    if (tid < 32) sBias[0   + tid] = ab1[tid];
    if (tid < 32) sBias[32  + tid] = ab2[tid];
    if (tid < 8)  sBias[64  + tid] = (tid < 4) ? ab3[tid] : 0.f;
    if (tid < 16) sBias[72  + tid] = pb1[tid];
    if (tid < 16) sBias[88  + tid] = pb2[tid];
    if (tid < 16) sBias[104 + tid] = pb3[tid];
    if (tid < 16) sBias[120 + tid] = g_dbias[ray*16 + tid];
    if (tid < 16) sBias[136 + tid] = db2[tid];
    if (tid < 16) sBias[152 + tid] = db3[tid];
    if (tid < 8)  sBias[168 + tid] = (tid < 3) ? db4[tid] : 0.f;
    if (tid < 3)  s_ray[tid] = g_rayinfo[4*ray + tid];
    if (tid >= 3 && tid < 6) s_ray[tid] = ro[3*ray + (tid-3)];
    if (tid >= 6 && tid < 9) s_ray[tid] = rd[3*ray + (tid-6)];
    __syncthreads();

    int lane = tid & 31, wid = tid >> 5;
    int sbase_w = blockIdx.x * 256 + wid * 32;
    int s = sbase_w + lane;

    float tmn = s_ray[0], rn = s_ray[1], mask = s_ray[2];
    float it = tmn + STEPW * (float)s / rn;
    float px = s_ray[3] + s_ray[6] * it;
    float py = s_ray[4] + s_ray[7] * it;
    float pz = s_ray[5] + s_ray[8] * it;
    bool inb = (s < NS) && (mask == 0.f) &&
               px >= -1.f && px <= 1.f &&
               py >= -1.f && py <= 1.f &&
               pz >= -1.f && pz <= 1.f;
    unsigned ball = __ballot_sync(0xFFFFFFFFu, inb);
    if (ball == 0u) {
        if (s < NS) g_scratch[ray*NS + s] = make_float4(0.f, 0.f, 0.f, 0.f);
        return;
    }

    // ---- trilerp (per-lane) ----
    float xs16[16];
#pragma unroll
    for (int k = 0; k < 16; k++) xs16[k] = 0.f;
    if (inb) {
        float gx = (px + 1.f) * 0.5f * 159.f;
        float gy = (py + 1.f) * 0.5f * 159.f;
        float gz = (pz + 1.f) * 0.5f * 159.f;
        float fx0 = floorf(gx), fy0 = floorf(gy), fz0 = floorf(gz);
        float wx1 = gx - fx0, wy1 = gy - fy0, wz1 = gz - fz0;
        float wx0 = 1.f - wx1, wy0 = 1.f - wy1, wz0 = 1.f - wz1;
        int ix0 = min(max((int)fx0, 0), 159); int ix1 = min(ix0 + 1, 159);
        int iy0 = min(max((int)fy0, 0), 159); int iy1 = min(iy0 + 1, 159);
        int iz0 = min(max((int)fz0, 0), 159); int iz1 = min(iz0 + 1, 159);

        u64 lat2[6];
#pragma unroll
        for (int k = 0; k < 6; k++) lat2[k] = 0ull;

#define ADD_CORNER(X, Y, Z, W) {                                                     \
            const u64* gp = reinterpret_cast<const u64*>(                            \
                g_grid_h + (size_t)((((X)*160 + (Y))*160) + (Z)) * 12);              \
            u64 A = __ldg(gp), B = __ldg(gp+1), C = __ldg(gp+2);                     \
            float W_ = (W);                                                          \
            u64 wb = pk2(W_, W_);                                                    \
            u64 f0, f1;                                                              \
            h4_to_f2x2(A, f0, f1); fma2(lat2[0], wb, f0); fma2(lat2[1], wb, f1);     \
            h4_to_f2x2(B, f0, f1); fma2(lat2[2], wb, f0); fma2(lat2[3], wb, f1);     \
            h4_to_f2x2(C, f0, f1); fma2(lat2[4], wb, f0); fma2(lat2[5], wb, f1); }

        ADD_CORNER(ix0, iy0, iz0, wx0*wy0*wz0);
        ADD_CORNER(ix0, iy0, iz1, wx0*wy0*wz1);
        ADD_CORNER(ix0, iy1, iz0, wx0*wy1*wz0);
        ADD_CORNER(ix0, iy1, iz1, wx0*wy1*wz1);
        ADD_CORNER(ix1, iy0, iz0, wx1*wy0*wz0);
        ADD_CORNER(ix1, iy0, iz1, wx1*wy0*wz1);
        ADD_CORNER(ix1, iy1, iz0, wx1*wy1*wz0);
        ADD_CORNER(ix1, iy1, iz1, wx1*wy1*wz1);
#undef ADD_CORNER

        xs16[0] = pz; xs16[1] = py; xs16[2] = px;
#pragma unroll
        for (int k = 0; k < 6; k++) upk2(lat2[k], xs16[3 + 2*k], xs16[4 + 2*k]);
    }

    // ---- stage xin (16 halfs = 8 u32 per sample) ----
#pragma unroll
    for (int j = 0; j < 8; j++)
        sXu[wid][lane][j] = cvt2h(xs16[2*j], xs16[2*j+1]);
    __syncwarp();

    float inbf = inb ? 1.f : 0.f;
    const u32* xw = &sXu[wid][0][0];
    int t4 = lane & 3, rq = lane >> 2;

    for (int mt = 0; mt < 2; mt++) {
        // A_x fragment
        u32 ax[1][4];
        int rr = mt*16 + rq;
        ax[0][0] = xw[rr*8 + t4];
        ax[0][1] = xw[(rr+8)*8 + t4];
        ax[0][2] = xw[rr*8 + t4 + 4];
        ax[0][3] = xw[(rr+8)*8 + t4 + 4];

        // attention: 15->32->32->4
        float ca1[4][4]; u32 ah1[2][4];
        mlayer<1,4>(ax, ca1, sB, 0, &sBias[0], lane);
        relu_pack<2>(ca1, ah1);
        float ca2[4][4]; u32 ah2[2][4];
        mlayer<2,4>(ah1, ca2, sB, 4, &sBias[32], lane);
        relu_pack<2>(ca2, ah2);
        float ca3[1][4];
        mlayer<2,1>(ah2, ca3, sB, 12, &sBias[64], lane);

        // pos: 12->16->16->16
        float cp1[2][4]; u32 ap1[1][4];
        mlayer<1,2>(ax, cp1, sB, 14, &sBias[72], lane);
        relu_pack<1>(cp1, ap1);
        float cp2[2][4]; u32 ap2[1][4];
        mlayer<1,2>(ap1, cp2, sB, 16, &sBias[88], lane);
        relu_pack<1>(cp2, ap2);
        float cp3[2][4]; u32 ap3[1][4];
        mlayer<1,2>(ap2, cp3, sB, 18, &sBias[104], lane);
        pack_norelu<1>(cp3, ap3);

        // dir: p3(16, row0-zero weights) ->16->16->16->3
        float cd1[2][4]; u32 ad1[1][4];
        mlayer<1,2>(ap3, cd1, sB, 20, &sBias[120], lane);
        relu_pack<1>(cd1, ad1);
        float cd2[2][4]; u32 ad2[1][4];
        mlayer<1,2>(ad1, cd2, sB, 22, &sBias[136], lane);
        relu_pack<1>(cd2, ad2);
        float cd3[2][4]; u32 ad3[1][4];
        mlayer<1,2>(ad2, cd3, sB, 24, &sBias[152], lane);
        relu_pack<1>(cd3, ad3);
        float cd4[1][4];
        mlayer<1,1>(ad3, cd4, sB, 26, &sBias[168], lane);

        // ---- softmax over attention cols 0-3 (quad: t4 0<->1) ----
        float x0 = ca3[0][0], x1 = ca3[0][1], x2 = ca3[0][2], x3 = ca3[0][3];
        float m_lo  = fmaxf(x0, x1);
        float m_lop = __shfl_xor_sync(0xFFFFFFFFu, m_lo, 1);
        float mxa   = fmaxf(m_lo, m_lop);
        float e_s   = expf(x0 - mxa) + expf(x1 - mxa);
        float e_p   = __shfl_xor_sync(0xFFFFFFFFu, e_s, 1);
        float att_r = expf(x1 - mxa) / (e_s + e_p);      // valid at t4==0

        float m_hi  = fmaxf(x2, x3);
        float m_hip = __shfl_xor_sync(0xFFFFFFFFu, m_hi, 1);
        float mxb   = fmaxf(m_hi, m_hip);
        float e2_s  = expf(x2 - mxb) + expf(x3 - mxb);
        float e2_p  = __shfl_xor_sync(0xFFFFFFFFu, e2_s, 1);
        float att_r8 = expf(x3 - mxb) / (e2_s + e2_p);   // valid at t4==0

        // rgb col2 from t4==1 partner
        float col2_r  = __shfl_xor_sync(0xFFFFFFFFu, cd4[0][0], 1);
        float col2_r8 = __shfl_xor_sync(0xFFFFFFFFu, cd4[0][2], 1);

        // inb flags of the two rows
        float inb_r  = __shfl_sync(0xFFFFFFFFu, inbf, mt*16 + rq);
        float inb_r8 = __shfl_sync(0xFFFFFFFFu, inbf, mt*16 + rq + 8);

        if (t4 == 0) {
            int s0 = sbase_w + mt*16 + rq;
            if (s0 < NS)
                g_scratch[ray*NS + s0] =
                    shade(att_r, cp3[0][0], cd4[0][0], cd4[0][1], col2_r, inb_r);
            int s1 = s0 + 8;
            if (s1 < NS)
                g_scratch[ray*NS + s1] =
                    shade(att_r8, cp3[0][2], cd4[0][2], cd4[0][3], col2_r8, inb_r8);
        }
    }
}

// =====================================================================
// Kernel 3: warp-per-ray alpha compositing
// =====================================================================
__global__ __launch_bounds__(256) void k_phaseB(float* __restrict__ out) {
    int gid  = blockIdx.x * blockDim.x + threadIdx.x;
    int ray  = gid >> 5;
    int lane = gid & 31;
    if (ray >= NRAY) return;

    float tmn = g_rayinfo[4*ray], rn = g_rayinfo[4*ray+1];
    float base_depth = tmn * rn;

    float T = 1.f;
    float sr = 0.f, sg = 0.f, sb = 0.f, sd = 0.f, sa = 0.f;

    for (int c0 = 0; c0 < NS; c0 += 32) {
        int s = c0 + lane;
        float4 rec = make_float4(0.f, 0.f, 0.f, 0.f);
        if (s < NS) rec = g_scratch[ray*NS + s];
        float a = rec.x;
        float q = fmaxf(1.f - a, 1e-10f);
        float ip = q;
#pragma unroll
        for (int off = 1; off < 32; off <<= 1) {
            float v = __shfl_up_sync(0xFFFFFFFFu, ip, off);
            if (lane >= off) ip *= v;
        }
        float ep = __shfl_up_sync(0xFFFFFFFFu, ip, 1);
        if (lane == 0) ep = 1.f;
        float w = a * T * ep;
        sr += w * rec.y;
        sg += w * rec.z;
        sb += w * rec.w;
        sd += w * (base_depth + STEPW * (float)s);
        sa += w;
        T *= __shfl_sync(0xFFFFFFFFu, ip, 31);
    }

#pragma unroll
    for (int off = 16; off > 0; off >>= 1) {
        sr += __shfl_xor_sync(0xFFFFFFFFu, sr, off);
        sg += __shfl_xor_sync(0xFFFFFFFFu, sg, off);
        sb += __shfl_xor_sync(0xFFFFFFFFu, sb, off);
        sd += __shfl_xor_sync(0xFFFFFFFFu, sd, off);
        sa += __shfl_xor_sync(0xFFFFFFFFu, sa, off);
    }

    if (lane == 0) {
        float depth = sd + T * FARC;
        out[ray*6+0] = sr + T * BGC;
        out[ray*6+1] = sg + T * BGC;
        out[ray*6+2] = sb + T * BGC;
        out[ray*6+3] = depth;
        out[ray*6+4] = 1.f / depth;
        out[ray*6+5] = sa;
    }
}

// =====================================================================
extern "C" void kernel_launch(void* const* d_in, const int* in_sizes, int n_in,
                              void* d_out, int out_size) {
    const float* ro  = (const float*)d_in[0];
    const float* rd  = (const float*)d_in[1];
    const float* vd  = (const float*)d_in[2];
    const float* grd = (const float*)d_in[3];
    const float* aw1 = (const float*)d_in[4];
    const float* ab1 = (const float*)d_in[5];
    const float* aw2 = (const float*)d_in[6];
    const float* ab2 = (const float*)d_in[7];
    const float* aw3 = (const float*)d_in[8];
    const float* ab3 = (const float*)d_in[9];
    const float* pw1 = (const float*)d_in[10];
    const float* pb1 = (const float*)d_in[11];
    const float* pw2 = (const float*)d_in[12];
    const float* pb2 = (const float*)d_in[13];
    const float* pw3 = (const float*)d_in[14];
    const float* pb3 = (const float*)d_in[15];
    const float* dw1 = (const float*)d_in[16];
    const float* db1 = (const float*)d_in[17];
    const float* dw2 = (const float*)d_in[18];
    const float* db2 = (const float*)d_in[19];
    const float* dw3 = (const float*)d_in[20];
    const float* db3 = (const float*)d_in[21];
    const float* dw4 = (const float*)d_in[22];
    const float* db4 = (const float*)d_in[23];

    k_transpose<<<R3 / 256, 256>>>(grd);
    k_raypre<<<(NRAY + 255) / 256, 256>>>(ro, rd, vd, dw1, db1);
    dim3 gA((NS + 255) / 256, NRAY);
    k_phaseA<<<gA, 256>>>(ro, rd,
                          aw1, ab1, aw2, ab2, aw3, ab3,
                          pw1, pb1, pw2, pb2, pw3, pb3,
                          dw1, dw2, db2, dw3, db3, dw4, db4);
    k_phaseB<<<(NRAY * 32) / 256, 256>>>((float*)d_out);
}

// round 17
// speedup vs baseline: 2.6130x; 1.1435x over previous
#include <cuda_runtime.h>
#include <cuda_fp16.h>
#include <math.h>

#define RES   160
#define R3    (RES*RES*RES)
#define NRAY  2048
#define NS    558
#define NEARC 0.05f
#define FARC  3.5f
#define BGC   1.0f
#define STEPW 0.00625f                 /* STEPSIZE * VOXEL = 0.5 * 0.0125 */
#define ACT_SHIFT -4.5951198501345898f /* log(1/(1-0.01)-1) */

typedef unsigned long long u64;
typedef unsigned int u32;

// ---- packed f32x2 helpers (trilerp) ----
__device__ __forceinline__ u64 pk2(float lo, float hi) {
    u64 r; asm("mov.b64 %0, {%1, %2};" : "=l"(r) : "f"(lo), "f"(hi)); return r;
}
__device__ __forceinline__ void upk2(u64 v, float& lo, float& hi) {
    asm("mov.b64 {%0, %1}, %2;" : "=f"(lo), "=f"(hi) : "l"(v));
}
__device__ __forceinline__ void fma2(u64& d, u64 a, u64 b) {
    asm("fma.rn.f32x2 %0, %1, %2, %0;" : "+l"(d) : "l"(a), "l"(b));
}
__device__ __forceinline__ void h4_to_f2x2(u64 h4, u64& lo2, u64& hi2) {
    u32 l = (u32)h4, h = (u32)(h4 >> 32);
    __half2 hl = *reinterpret_cast<__half2*>(&l);
    __half2 hh = *reinterpret_cast<__half2*>(&h);
    float2 fl = __half22float2(hl);
    float2 fh = __half22float2(hh);
    lo2 = pk2(fl.x, fl.y);
    hi2 = pk2(fh.x, fh.y);
}

// ---- mma helpers ----
__device__ __forceinline__ void mma16816(float c[4], const u32 a[4], u32 b0, u32 b1) {
    asm volatile(
        "mma.sync.aligned.m16n8k16.row.col.f32.f16.f16.f32 "
        "{%0,%1,%2,%3}, {%4,%5,%6,%7}, {%8,%9}, {%0,%1,%2,%3};"
        : "+f"(c[0]), "+f"(c[1]), "+f"(c[2]), "+f"(c[3])
        : "r"(a[0]), "r"(a[1]), "r"(a[2]), "r"(a[3]), "r"(b0), "r"(b1));
}
__device__ __forceinline__ u32 cvt2h(float lo, float hi) {
    u32 r; asm("cvt.rn.f16x2.f32 %0, %1, %2;" : "=r"(r) : "f"(hi), "f"(lo)); return r;
}

// ---- device scratch ----
__device__ __half g_grid_h[(size_t)R3 * 12];
__device__ float  g_rayinfo[NRAY * 4];
__device__ float  g_dbias[NRAY * 16];

// =====================================================================
// Kernel 0: transpose grid fp32 (C,R,R,R) -> fp16 (R,R,R,C)
// =====================================================================
__global__ __launch_bounds__(256) void k_transpose(const float* __restrict__ g) {
    __shared__ __align__(16) __half tile[256 * 12];
    int v0 = blockIdx.x * 256;
    int t  = threadIdx.x;
    int v  = v0 + t;
#pragma unroll
    for (int c = 0; c < 12; c++)
        tile[t * 12 + c] = __float2half_rn(__ldg(g + (size_t)c * R3 + v));
    __syncthreads();
    u32* dst = reinterpret_cast<u32*>(g_grid_h + (size_t)v0 * 12);
    const u32* src = reinterpret_cast<const u32*>(tile);
#pragma unroll
    for (int i = 0; i < 6; i++)
        dst[i * 256 + t] = src[i * 256 + t];
}

// =====================================================================
// Kernel 1: per-ray precompute
// =====================================================================
__global__ void k_raypre(const float* __restrict__ ro, const float* __restrict__ rd,
                         const float* __restrict__ vd, const float* __restrict__ dw1,
                         const float* __restrict__ db1) {
    int r = blockIdx.x * blockDim.x + threadIdx.x;
    if (r >= NRAY) return;
    float ox = ro[3*r], oy = ro[3*r+1], oz = ro[3*r+2];
    float dx = rd[3*r], dy = rd[3*r+1], dz = rd[3*r+2];
    float vx = (dx == 0.f) ? 1e-6f : dx;
    float vy = (dy == 0.f) ? 1e-6f : dy;
    float vz = (dz == 0.f) ? 1e-6f : dz;
    float rax = (1.f - ox) / vx, rbx = (-1.f - ox) / vx;
    float ray_ = (1.f - oy) / vy, rby = (-1.f - oy) / vy;
    float raz = (1.f - oz) / vz, rbz = (-1.f - oz) / vz;
    float tmn = fmaxf(fmaxf(fminf(rax, rbx), fminf(ray_, rby)), fminf(raz, rbz));
    float tmx = fminf(fminf(fmaxf(rax, rbx), fmaxf(ray_, rby)), fmaxf(raz, rbz));
    tmn = fminf(fmaxf(tmn, NEARC), FARC);
    tmx = fminf(fmaxf(tmx, NEARC), FARC);
    float mask = (tmx <= tmn) ? 1.f : 0.f;
    float nn = sqrtf(dx*dx + dy*dy + dz*dz);
    g_rayinfo[4*r+0] = tmn;
    g_rayinfo[4*r+1] = nn;
    g_rayinfo[4*r+2] = mask;
    g_rayinfo[4*r+3] = 0.f;

    float wx = vd[3*r], wy = vd[3*r+1], wz = vd[3*r+2];
    float emb[39];
    emb[0] = wx; emb[1] = wy; emb[2] = wz;
    float f = 1.f;
#pragma unroll
    for (int l = 0; l < 6; l++) {
        emb[3+6*l+0] = sinf(wx*f); emb[3+6*l+1] = sinf(wy*f); emb[3+6*l+2] = sinf(wz*f);
        emb[3+6*l+3] = cosf(wx*f); emb[3+6*l+4] = cosf(wy*f); emb[3+6*l+5] = cosf(wz*f);
        f *= 2.f;
    }
#pragma unroll
    for (int j = 0; j < 16; j++) {
        float acc = db1[j];
#pragma unroll
        for (int k = 0; k < 39; k++) acc += emb[k] * dw1[(15+k)*16 + j];
        g_dbias[16*r + j] = acc;
    }
}

// =====================================================================
// Kernel 2 (fused): MLPs via warp-level fp16 MMA + in-block compositing
// one block (256 thr) per ray; warps loop 3 chunks of 32 samples
// =====================================================================

template<int KT, int NT>
__device__ __forceinline__ void mlayer(const u32 A[][4], float C[][4],
                                       const u32* sB, int tileBase,
                                       const float* bias, int lane) {
    int t4 = lane & 3;
#pragma unroll
    for (int nt = 0; nt < NT; nt++) {
        float b0 = bias[nt*8 + 2*t4];
        float b1 = bias[nt*8 + 2*t4 + 1];
        C[nt][0] = b0; C[nt][1] = b1; C[nt][2] = b0; C[nt][3] = b1;
#pragma unroll
        for (int kt = 0; kt < KT; kt++) {
            int ti = tileBase + kt*NT + nt;
            mma16816(C[nt], A[kt], sB[ti*64 + lane*2], sB[ti*64 + lane*2 + 1]);
        }
    }
}

template<int NF>
__device__ __forceinline__ void relu_pack(const float C[][4], u32 A[][4]) {
#pragma unroll
    for (int f = 0; f < NF; f++) {
        A[f][0] = cvt2h(fmaxf(C[2*f][0], 0.f),   fmaxf(C[2*f][1], 0.f));
        A[f][1] = cvt2h(fmaxf(C[2*f][2], 0.f),   fmaxf(C[2*f][3], 0.f));
        A[f][2] = cvt2h(fmaxf(C[2*f+1][0], 0.f), fmaxf(C[2*f+1][1], 0.f));
        A[f][3] = cvt2h(fmaxf(C[2*f+1][2], 0.f), fmaxf(C[2*f+1][3], 0.f));
    }
}
template<int NF>
__device__ __forceinline__ void pack_norelu(const float C[][4], u32 A[][4]) {
#pragma unroll
    for (int f = 0; f < NF; f++) {
        A[f][0] = cvt2h(C[2*f][0],   C[2*f][1]);
        A[f][1] = cvt2h(C[2*f][2],   C[2*f][3]);
        A[f][2] = cvt2h(C[2*f+1][0], C[2*f+1][1]);
        A[f][3] = cvt2h(C[2*f+1][2], C[2*f+1][3]);
    }
}

__device__ __forceinline__ float4 shade(float att, float dens, float r0, float r1,
                                        float r2, float inb) {
    if (inb == 0.f) return make_float4(0.f, 0.f, 0.f, 0.f);
    float d = att * dens;
    float xs = d + ACT_SHIFT;
    float sp = fmaxf(xs, 0.f) + log1pf(expf(-fabsf(xs)));
    float alpha = 1.f - expf(-sp * 0.5f);
    float c0 = 1.f / (1.f + expf(-att * r0));
    float c1 = 1.f / (1.f + expf(-att * r1));
    float c2 = 1.f / (1.f + expf(-att * r2));
    return make_float4(alpha, c0, c1, c2);
}

__global__ __launch_bounds__(256) void k_main(
    const float* __restrict__ ro, const float* __restrict__ rd,
    const float* __restrict__ aw1, const float* __restrict__ ab1,
    const float* __restrict__ aw2, const float* __restrict__ ab2,
    const float* __restrict__ aw3, const float* __restrict__ ab3,
    const float* __restrict__ pw1, const float* __restrict__ pb1,
    const float* __restrict__ pw2, const float* __restrict__ pb2,
    const float* __restrict__ pw3, const float* __restrict__ pb3,
    const float* __restrict__ dw1,
    const float* __restrict__ dw2, const float* __restrict__ db2,
    const float* __restrict__ dw3, const float* __restrict__ db3,
    const float* __restrict__ dw4, const float* __restrict__ db4,
    float* __restrict__ out)
{
    __shared__ u32  sB[27 * 64];
    __shared__ u32  sXu[8][32][8];
    __shared__ float sBias[176];
    __shared__ float s_ray[9];
    __shared__ __align__(16) float4 s_samp[NS];

    int tid = threadIdx.x;
    int ray = blockIdx.x;

    // ---- stage B fragments ----
    for (int e = tid; e < 27*64; e += 256) {
        int tile = e >> 6, li = (e >> 1) & 31, reg = e & 1;
        int t4 = li & 3, gq = li >> 2;
        const float* W; int stride, Oreal, klo, khi, ksh, kbase, nbase;
        if (tile < 4)       { W=aw1; stride=32; Oreal=32; klo=0; khi=15; ksh=0; kbase=0;            nbase=tile*8; }
        else if (tile < 12) { int t=tile-4;  W=aw2; stride=32; Oreal=32; klo=0; khi=32; ksh=0; kbase=(t>>2)*16; nbase=(t&3)*8; }
        else if (tile < 14) { int t=tile-12; W=aw3; stride=4;  Oreal=4;  klo=0; khi=32; ksh=0; kbase=t*16;      nbase=0; }
        else if (tile < 16) { int t=tile-14; W=pw1; stride=16; Oreal=16; klo=3; khi=15; ksh=3; kbase=0;         nbase=t*8; }
        else if (tile < 18) { int t=tile-16; W=pw2; stride=16; Oreal=16; klo=0; khi=16; ksh=0; kbase=0;         nbase=t*8; }
        else if (tile < 20) { int t=tile-18; W=pw3; stride=16; Oreal=16; klo=0; khi=16; ksh=0; kbase=0;         nbase=t*8; }
        else if (tile < 22) { int t=tile-20; W=dw1; stride=16; Oreal=16; klo=1; khi=16; ksh=1; kbase=0;         nbase=t*8; }
        else if (tile < 24) { int t=tile-22; W=dw2; stride=16; Oreal=16; klo=0; khi=16; ksh=0; kbase=0;         nbase=t*8; }
        else if (tile < 26) { int t=tile-24; W=dw3; stride=16; Oreal=16; klo=0; khi=16; ksh=0; kbase=0;         nbase=t*8; }
        else                {               W=dw4; stride=3;  Oreal=3;  klo=0; khi=16; ksh=0; kbase=0;         nbase=0; }
        int k0 = kbase + t4*2 + reg*8;
        int n  = nbase + gq;
        float v0 = 0.f, v1 = 0.f;
        if (n < Oreal) {
            int ka = k0, kb = k0 + 1;
            if (ka >= klo && ka < khi) v0 = W[(ka-ksh)*stride + n];
            if (kb >= klo && kb < khi) v1 = W[(kb-ksh)*stride + n];
        }
        sB[e] = cvt2h(v0, v1);
    }
    if (tid < 32) sBias[0   + tid] = ab1[tid];
    if (tid < 32) sBias[32  + tid] = ab2[tid];
    if (tid < 8)  sBias[64  + tid] = (tid < 4) ? ab3[tid] : 0.f;
    if (tid < 16) sBias[72  + tid] = pb1[tid];
    if (tid < 16) sBias[88  + tid] = pb2[tid];
    if (tid < 16) sBias[104 + tid] = pb3[tid];
    if (tid < 16) sBias[120 + tid] = g_dbias[ray*16 + tid];
    if (tid < 16) sBias[136 + tid] = db2[tid];
    if (tid < 16) sBias[152 + tid] = db3[tid];
    if (tid < 8)  sBias[168 + tid] = (tid < 3) ? db4[tid] : 0.f;
    if (tid < 3)  s_ray[tid] = g_rayinfo[4*ray + tid];
    if (tid >= 3 && tid < 6) s_ray[tid] = ro[3*ray + (tid-3)];
    if (tid >= 6 && tid < 9) s_ray[tid] = rd[3*ray + (tid-6)];
    __syncthreads();

    int lane = tid & 31, wid = tid >> 5;
    float tmn = s_ray[0], rn = s_ray[1], mask = s_ray[2];
    int t4 = lane & 3, rq = lane >> 2;

    for (int c = 0; c < 3; c++) {
        int sbase_w = c * 256 + wid * 32;
        if (sbase_w >= NS) break;
        int s = sbase_w + lane;

        float it = tmn + STEPW * (float)s / rn;
        float px = s_ray[3] + s_ray[6] * it;
        float py = s_ray[4] + s_ray[7] * it;
        float pz = s_ray[5] + s_ray[8] * it;
        bool inb = (s < NS) && (mask == 0.f) &&
                   px >= -1.f && px <= 1.f &&
                   py >= -1.f && py <= 1.f &&
                   pz >= -1.f && pz <= 1.f;
        unsigned ball = __ballot_sync(0xFFFFFFFFu, inb);
        if (ball == 0u) {
            if (s < NS) s_samp[s] = make_float4(0.f, 0.f, 0.f, 0.f);
            continue;
        }

        // ---- trilerp ----
        float xs16[16];
#pragma unroll
        for (int k = 0; k < 16; k++) xs16[k] = 0.f;
        if (inb) {
            float gx = (px + 1.f) * 0.5f * 159.f;
            float gy = (py + 1.f) * 0.5f * 159.f;
            float gz = (pz + 1.f) * 0.5f * 159.f;
            float fx0 = floorf(gx), fy0 = floorf(gy), fz0 = floorf(gz);
            float wx1 = gx - fx0, wy1 = gy - fy0, wz1 = gz - fz0;
            float wx0 = 1.f - wx1, wy0 = 1.f - wy1, wz0 = 1.f - wz1;
            int ix0 = min(max((int)fx0, 0), 159); int ix1 = min(ix0 + 1, 159);
            int iy0 = min(max((int)fy0, 0), 159); int iy1 = min(iy0 + 1, 159);
            int iz0 = min(max((int)fz0, 0), 159); int iz1 = min(iz0 + 1, 159);

            u64 lat2[6];
#pragma unroll
            for (int k = 0; k < 6; k++) lat2[k] = 0ull;

#define ADD_CORNER(X, Y, Z, W) {                                                     \
                const u64* gp = reinterpret_cast<const u64*>(                        \
                    g_grid_h + (size_t)((((X)*160 + (Y))*160) + (Z)) * 12);          \
                u64 A = __ldg(gp), B = __ldg(gp+1), C = __ldg(gp+2);                 \
                float W_ = (W);                                                      \
                u64 wb = pk2(W_, W_);                                                \
                u64 f0, f1;                                                          \
                h4_to_f2x2(A, f0, f1); fma2(lat2[0], wb, f0); fma2(lat2[1], wb, f1); \
                h4_to_f2x2(B, f0, f1); fma2(lat2[2], wb, f0); fma2(lat2[3], wb, f1); \
                h4_to_f2x2(C, f0, f1); fma2(lat2[4], wb, f0); fma2(lat2[5], wb, f1); }

            ADD_CORNER(ix0, iy0, iz0, wx0*wy0*wz0);
            ADD_CORNER(ix0, iy0, iz1, wx0*wy0*wz1);
            ADD_CORNER(ix0, iy1, iz0, wx0*wy1*wz0);
            ADD_CORNER(ix0, iy1, iz1, wx0*wy1*wz1);
            ADD_CORNER(ix1, iy0, iz0, wx1*wy0*wz0);
            ADD_CORNER(ix1, iy0, iz1, wx1*wy0*wz1);
            ADD_CORNER(ix1, iy1, iz0, wx1*wy1*wz0);
            ADD_CORNER(ix1, iy1, iz1, wx1*wy1*wz1);
#undef ADD_CORNER

            xs16[0] = pz; xs16[1] = py; xs16[2] = px;
#pragma unroll
            for (int k = 0; k < 6; k++) upk2(lat2[k], xs16[3 + 2*k], xs16[4 + 2*k]);
        }

#pragma unroll
        for (int j = 0; j < 8; j++)
            sXu[wid][lane][j] = cvt2h(xs16[2*j], xs16[2*j+1]);
        __syncwarp();

        float inbf = inb ? 1.f : 0.f;
        const u32* xw = &sXu[wid][0][0];

        for (int mt = 0; mt < 2; mt++) {
            u32 ax[1][4];
            int rr = mt*16 + rq;
            ax[0][0] = xw[rr*8 + t4];
            ax[0][1] = xw[(rr+8)*8 + t4];
            ax[0][2] = xw[rr*8 + t4 + 4];
            ax[0][3] = xw[(rr+8)*8 + t4 + 4];

            float ca1[4][4]; u32 ah1[2][4];
            mlayer<1,4>(ax, ca1, sB, 0, &sBias[0], lane);
            relu_pack<2>(ca1, ah1);
            float ca2[4][4]; u32 ah2[2][4];
            mlayer<2,4>(ah1, ca2, sB, 4, &sBias[32], lane);
            relu_pack<2>(ca2, ah2);
            float ca3[1][4];
            mlayer<2,1>(ah2, ca3, sB, 12, &sBias[64], lane);

            float cp1[2][4]; u32 ap1[1][4];
            mlayer<1,2>(ax, cp1, sB, 14, &sBias[72], lane);
            relu_pack<1>(cp1, ap1);
            float cp2[2][4]; u32 ap2[1][4];
            mlayer<1,2>(ap1, cp2, sB, 16, &sBias[88], lane);
            relu_pack<1>(cp2, ap2);
            float cp3[2][4]; u32 ap3[1][4];
            mlayer<1,2>(ap2, cp3, sB, 18, &sBias[104], lane);
            pack_norelu<1>(cp3, ap3);

            float cd1[2][4]; u32 ad1[1][4];
            mlayer<1,2>(ap3, cd1, sB, 20, &sBias[120], lane);
            relu_pack<1>(cd1, ad1);
            float cd2[2][4]; u32 ad2[1][4];
            mlayer<1,2>(ad1, cd2, sB, 22, &sBias[136], lane);
            relu_pack<1>(cd2, ad2);
            float cd3[2][4]; u32 ad3[1][4];
            mlayer<1,2>(ad2, cd3, sB, 24, &sBias[152], lane);
            relu_pack<1>(cd3, ad3);
            float cd4[1][4];
            mlayer<1,1>(ad3, cd4, sB, 26, &sBias[168], lane);

            float x0 = ca3[0][0], x1 = ca3[0][1], x2 = ca3[0][2], x3 = ca3[0][3];
            float m_lo  = fmaxf(x0, x1);
            float m_lop = __shfl_xor_sync(0xFFFFFFFFu, m_lo, 1);
            float mxa   = fmaxf(m_lo, m_lop);
            float e_s   = expf(x0 - mxa) + expf(x1 - mxa);
            float e_p   = __shfl_xor_sync(0xFFFFFFFFu, e_s, 1);
            float att_r = expf(x1 - mxa) / (e_s + e_p);

            float m_hi  = fmaxf(x2, x3);
            float m_hip = __shfl_xor_sync(0xFFFFFFFFu, m_hi, 1);
            float mxb   = fmaxf(m_hi, m_hip);
            float e2_s  = expf(x2 - mxb) + expf(x3 - mxb);
            float e2_p  = __shfl_xor_sync(0xFFFFFFFFu, e2_s, 1);
            float att_r8 = expf(x3 - mxb) / (e2_s + e2_p);

            float col2_r  = __shfl_xor_sync(0xFFFFFFFFu, cd4[0][0], 1);
            float col2_r8 = __shfl_xor_sync(0xFFFFFFFFu, cd4[0][2], 1);

            float inb_r  = __shfl_sync(0xFFFFFFFFu, inbf, mt*16 + rq);
            float inb_r8 = __shfl_sync(0xFFFFFFFFu, inbf, mt*16 + rq + 8);

            if (t4 == 0) {
                int s0 = sbase_w + mt*16 + rq;
                if (s0 < NS)
                    s_samp[s0] = shade(att_r, cp3[0][0], cd4[0][0], cd4[0][1],
                                       col2_r, inb_r);
                int s1 = s0 + 8;
                if (s1 < NS)
                    s_samp[s1] = shade(att_r8, cp3[0][2], cd4[0][2], cd4[0][3],
                                       col2_r8, inb_r8);
            }
        }
    }
    __syncthreads();

    // ---- compositing by warp 0 ----
    if (wid == 0) {
        float base_depth = tmn * rn;
        float T = 1.f;
        float sr = 0.f, sg = 0.f, sb = 0.f, sd = 0.f, sa = 0.f;

        for (int c0 = 0; c0 < NS; c0 += 32) {
            int s = c0 + lane;
            float4 rec = (s < NS) ? s_samp[s] : make_float4(0.f, 0.f, 0.f, 0.f);
            float a = rec.x;
            float q = fmaxf(1.f - a, 1e-10f);
            float ip = q;
#pragma unroll
            for (int off = 1; off < 32; off <<= 1) {
                float v = __shfl_up_sync(0xFFFFFFFFu, ip, off);
                if (lane >= off) ip *= v;
            }
            float ep = __shfl_up_sync(0xFFFFFFFFu, ip, 1);
            if (lane == 0) ep = 1.f;
            float w = a * T * ep;
            sr += w * rec.y;
            sg += w * rec.z;
            sb += w * rec.w;
            sd += w * (base_depth + STEPW * (float)s);
            sa += w;
            T *= __shfl_sync(0xFFFFFFFFu, ip, 31);
        }

#pragma unroll
        for (int off = 16; off > 0; off >>= 1) {
            sr += __shfl_xor_sync(0xFFFFFFFFu, sr, off);
            sg += __shfl_xor_sync(0xFFFFFFFFu, sg, off);
            sb += __shfl_xor_sync(0xFFFFFFFFu, sb, off);
            sd += __shfl_xor_sync(0xFFFFFFFFu, sd, off);
            sa += __shfl_xor_sync(0xFFFFFFFFu, sa, off);
        }

        if (lane == 0) {
            float depth = sd + T * FARC;
            out[ray*6+0] = sr + T * BGC;
            out[ray*6+1] = sg + T * BGC;
            out[ray*6+2] = sb + T * BGC;
            out[ray*6+3] = depth;
            out[ray*6+4] = 1.f / depth;
            out[ray*6+5] = sa;
        }
    }
}

// =====================================================================
extern "C" void kernel_launch(void* const* d_in, const int* in_sizes, int n_in,
                              void* d_out, int out_size) {
    const float* ro  = (const float*)d_in[0];
    const float* rd  = (const float*)d_in[1];
    const float* vd  = (const float*)d_in[2];
    const float* grd = (const float*)d_in[3];
    const float* aw1 = (const float*)d_in[4];
    const float* ab1 = (const float*)d_in[5];
    const float* aw2 = (const float*)d_in[6];
    const float* ab2 = (const float*)d_in[7];
    const float* aw3 = (const float*)d_in[8];
    const float* ab3 = (const float*)d_in[9];
    const float* pw1 = (const float*)d_in[10];
    const float* pb1 = (const float*)d_in[11];
    const float* pw2 = (const float*)d_in[12];
    const float* pb2 = (const float*)d_in[13];
    const float* pw3 = (const float*)d_in[14];
    const float* pb3 = (const float*)d_in[15];
    const float* dw1 = (const float*)d_in[16];
    const float* db1 = (const float*)d_in[17];
    const float* dw2 = (const float*)d_in[18];
    const float* db2 = (const float*)d_in[19];
    const float* dw3 = (const float*)d_in[20];
    const float* db3 = (const float*)d_in[21];
    const float* dw4 = (const float*)d_in[22];
    const float* db4 = (const float*)d_in[23];

    k_transpose<<<R3 / 256, 256>>>(grd);
    k_raypre<<<(NRAY + 255) / 256, 256>>>(ro, rd, vd, dw1, db1);
    k_main<<<NRAY, 256>>>(ro, rd,
                          aw1, ab1, aw2, ab2, aw3, ab3,
                          pw1, pb1, pw2, pb2, pw3, pb3,
                          dw1, dw2, db2, dw3, db3, dw4, db4,
                          (float*)d_out);
}